// round 5
// baseline (speedup 1.0000x reference)
#include <cuda_runtime.h>
#include <cuda_fp16.h>
#include <cstdint>

// ============================ problem constants ============================
namespace {
constexpr int B_SZ  = 16;
constexpr int LKDIM = 8192;
constexpr int DDIM  = 1024;
constexpr int HDIM  = 1024;
constexpr int BL    = B_SZ * LKDIM;          // 131072 GEMM rows

constexpr int M_TILE  = 128;
constexpr int N_TILE  = 256;                 // h-chunk per pass
constexpr int PASSES  = HDIM / N_TILE;       // 4
constexpr int K_HALF  = 64;                  // halves per K stage (128B rows)
constexpr int K_STEPS = DDIM / K_HALF;       // 16
constexpr int THREADS = 512;                 // 16 warps: 2(M) x 8(N)
constexpr int NUM_TILES = BL / M_TILE;       // 1024 CTAs

constexpr int A_BYTES = M_TILE * 128;        // 16 KB / stage
constexpr int B_BYTES = N_TILE * 128;        // 32 KB / stage

// dynamic SMEM layout
constexpr int OFF_Q   = 0;                       // 1024 f32
constexpr int OFF_WV  = OFF_Q  + HDIM * 4;       // 1024 f32
constexpr int OFF_OUT = OFF_WV + HDIM * 4;       // 128*4 f32 partial slots
constexpr int OFF_A   = 10240;                   // 1024-aligned
constexpr int OFF_B   = OFF_A + 2 * A_BYTES;     // +32KB
constexpr int SMEM_TOTAL = OFF_B + 2 * B_BYTES;  // 108544 B

// prep kernel split
constexpr int WCONV_BLOCKS = (HDIM * DDIM) / 256;   // 4096
constexpr int QPROJ_BLOCKS = B_SZ * 4;              // 64 (16 b x 4 h-chunks)
} // namespace

// ============================ device scratch ==============================
__device__ float  g_q [B_SZ * HDIM];   // projected queries (fp32, exact)
__device__ __half g_wt[HDIM * DDIM];   // W_k^T: [h][d] fp16

// ============================ helpers =====================================
__device__ __forceinline__ uint32_t smem_u32(const void* p) {
    uint32_t a;
    asm("{ .reg .u64 t; cvta.to.shared.u64 t, %1; cvt.u32.u64 %0, t; }"
        : "=r"(a) : "l"(p));
    return a;
}
__device__ __forceinline__ uint32_t swz128(uint32_t off) {
    return off ^ ((off >> 3) & 0x70);
}
__device__ __forceinline__ void ldm_x4(uint32_t& r0, uint32_t& r1,
                                       uint32_t& r2, uint32_t& r3, uint32_t addr) {
    asm volatile("ldmatrix.sync.aligned.m8n8.x4.shared.b16 {%0,%1,%2,%3}, [%4];"
                 : "=r"(r0), "=r"(r1), "=r"(r2), "=r"(r3) : "r"(addr));
}
__device__ __forceinline__ void mma16816(float* c, const uint32_t* a, const uint32_t* b) {
    asm volatile(
        "mma.sync.aligned.m16n8k16.row.col.f32.f16.f16.f32 "
        "{%0,%1,%2,%3}, {%4,%5,%6,%7}, {%8,%9}, {%0,%1,%2,%3};"
        : "+f"(c[0]), "+f"(c[1]), "+f"(c[2]), "+f"(c[3])
        : "r"(a[0]), "r"(a[1]), "r"(a[2]), "r"(a[3]), "r"(b[0]), "r"(b[1]));
}
__device__ __forceinline__ void cp_async16(uint32_t saddr, const void* gaddr) {
    asm volatile("cp.async.cg.shared.global [%0], [%1], 16;"
                 :: "r"(saddr), "l"(gaddr) : "memory");
}
#define CP_COMMIT() asm volatile("cp.async.commit_group;" ::: "memory")
#define CP_WAIT0()  asm volatile("cp.async.wait_group 0;"  ::: "memory")

__device__ __forceinline__ float fast_tanh(float x) {
    float r;
    asm("tanh.approx.f32 %0, %1;" : "=f"(r) : "f"(x));
    return r;
}

// frag loads for one kf slice (A: 4x ldm.x4, B: 2x ldm.x4)
__device__ __forceinline__ void load_frags(
    uint32_t a[4][4], uint32_t bb[4][2],
    uint32_t abase, uint32_t bbase,
    int rowA, int colA8, int rowB, int colB8, int kf)
{
    const int k0 = kf * 16;
#pragma unroll
    for (int mi = 0; mi < 4; mi++)
        ldm_x4(a[mi][0], a[mi][1], a[mi][2], a[mi][3],
               abase + swz128((uint32_t)((rowA + mi * 16) * 128 + (k0 + colA8) * 2)));
#pragma unroll
    for (int p = 0; p < 2; p++)
        ldm_x4(bb[2*p][0], bb[2*p][1], bb[2*p+1][0], bb[2*p+1][1],
               bbase + swz128((uint32_t)((rowB + p * 16) * 128 + (k0 + colB8) * 2)));
}

__device__ __forceinline__ void mma_all(float acc[4][4][4],
                                        uint32_t a[4][4], uint32_t bb[4][2])
{
#pragma unroll
    for (int mi = 0; mi < 4; mi++)
#pragma unroll
        for (int nf = 0; nf < 4; nf++)
            mma16816(acc[mi][nf], a[mi], bb[nf]);
}

// ============================ prep kernel (merged) =========================
__global__ void prep_kernel(const float* __restrict__ W_k,
                            const float* __restrict__ queries,
                            const float* __restrict__ W_q) {
    if (blockIdx.x < WCONV_BLOCKS) {
        int idx = blockIdx.x * 256 + threadIdx.x;   // over D*H
        int d = idx >> 10, h = idx & 1023;
        g_wt[(size_t)h * DDIM + d] = __float2half_rn(W_k[idx]);
    } else {
        const int qb = blockIdx.x - WCONV_BLOCKS;   // 0..63
        const int b  = qb >> 2;                     // batch
        const int h0 = (qb & 3) * 256;              // h-chunk base
        __shared__ float sq[DDIM];
        for (int i = threadIdx.x; i < DDIM; i += 256)
            sq[i] = queries[b * DDIM + i];
        __syncthreads();
        const int h = h0 + threadIdx.x;
        float acc = 0.f;
        const float* w = W_q + h;
#pragma unroll 8
        for (int d = 0; d < DDIM; d++)
            acc = fmaf(sq[d], w[(size_t)d * HDIM], acc);
        g_q[b * HDIM + h] = acc;
    }
}

// ============================ main fused kernel ===========================

// One K-stage: compute buffer CUR with kf-level register pipelining; load
// stage (KIDX+1) into buffer CUR^1 when HN.
#define STAGE(CUR, KIDX, HN)                                                 \
{                                                                            \
    const int ksv = (KIDX);                                                  \
    const bool hn = (HN);                                                    \
    float4 ar[4];                                                            \
    if (hn) {                                                                \
        const int k0n = (ksv + 1) * K_HALF;                                  \
        _Pragma("unroll")                                                    \
        for (int i = 0; i < 4; i++) {                                        \
            int idx = tid + i * THREADS;                                     \
            int hh = idx >> 3, c = idx & 7;                                  \
            cp_async16(sb + OFF_B + ((CUR) ^ 1) * B_BYTES +                  \
                           swz128((uint32_t)(hh * 128 + c * 16)),            \
                       g_wt + (size_t)(n0 + hh) * DDIM + k0n + c * 8);       \
        }                                                                    \
        CP_COMMIT();                                                         \
        _Pragma("unroll")                                                    \
        for (int i = 0; i < 4; i++)                                          \
            ar[i] = *reinterpret_cast<const float4*>(                        \
                keys + (size_t)(row0 + amRow[i]) * DDIM + k0n + amQ * 4);    \
    }                                                                        \
    const uint32_t abase = sb + OFF_A + (CUR) * A_BYTES;                     \
    const uint32_t bbase = sb + OFF_B + (CUR) * B_BYTES;                     \
    uint32_t afr[2][4][4], bfr[2][4][2];                                     \
    load_frags(afr[0], bfr[0], abase, bbase, rowA, colA8, rowB, colB8, 0);   \
    load_frags(afr[1], bfr[1], abase, bbase, rowA, colA8, rowB, colB8, 1);   \
    mma_all(acc, afr[0], bfr[0]);                                            \
    if (hn) {                                                                \
        _Pragma("unroll")                                                    \
        for (int i = 0; i < 4; i++) {                                        \
            union { __half2 hh2[2]; uint2 u; } cv;                           \
            cv.hh2[0] = __floats2half2_rn(ar[i].x, ar[i].y);                 \
            cv.hh2[1] = __floats2half2_rn(ar[i].z, ar[i].w);                 \
            *reinterpret_cast<uint2*>(smem + OFF_A + ((CUR) ^ 1) * A_BYTES + \
                swz128((uint32_t)(amRow[i] * 128 + amQ * 8))) = cv.u;        \
        }                                                                    \
    }                                                                        \
    load_frags(afr[0], bfr[0], abase, bbase, rowA, colA8, rowB, colB8, 2);   \
    mma_all(acc, afr[1], bfr[1]);                                            \
    load_frags(afr[1], bfr[1], abase, bbase, rowA, colA8, rowB, colB8, 3);   \
    mma_all(acc, afr[0], bfr[0]);                                            \
    mma_all(acc, afr[1], bfr[1]);                                            \
    CP_WAIT0();                                                              \
    __syncthreads();                                                         \
}

__global__ void __launch_bounds__(THREADS, 1)
attn_main_kernel(const float* __restrict__ keys,
                 const float* __restrict__ w_v,
                 float* __restrict__ out) {
    extern __shared__ char smem[];
    const uint32_t sb  = smem_u32(smem);
    const int tid  = threadIdx.x;
    const int wid  = tid >> 5;
    const int lane = tid & 31;
    const int warp_m = wid >> 3;     // 0..1
    const int warp_n = wid & 7;      // 0..7
    const int row0 = blockIdx.x * M_TILE;
    const int b    = row0 >> 13;     // 8192 rows per batch

    float* s_q   = reinterpret_cast<float*>(smem + OFF_Q);
    float* s_wv  = reinterpret_cast<float*>(smem + OFF_WV);
    float* s_out = reinterpret_cast<float*>(smem + OFF_OUT);  // [4][128]

    for (int i = tid; i < HDIM; i += THREADS) {
        s_q[i]  = g_q[b * HDIM + i];
        s_wv[i] = w_v[i];
    }

    // lane-invariant ldmatrix address pieces
    const int rowA  = warp_m * 64 + (lane & 15);
    const int colA8 = (lane >> 4) << 3;
    const int gB    = lane >> 3;
    const int rowB  = warp_n * 32 + (lane & 7) + ((gB >> 1) << 3);
    const int colB8 = (gB & 1) << 3;

    // A-loader indices: 4 x float4 per thread per stage
    const int amRow [4] = { (tid + 0*THREADS) >> 4, (tid + 1*THREADS) >> 4,
                            (tid + 2*THREADS) >> 4, (tid + 3*THREADS) >> 4 };
    const int amQ = tid & 15;

    float sc[8];
#pragma unroll
    for (int i = 0; i < 8; i++) sc[i] = 0.f;

    __syncthreads();   // publish s_q / s_wv

#pragma unroll 1
    for (int nc = 0; nc < PASSES; nc++) {
        const int n0 = nc * N_TILE;
        float acc[4][4][4];
#pragma unroll
        for (int mi = 0; mi < 4; mi++)
#pragma unroll
            for (int nf = 0; nf < 4; nf++)
#pragma unroll
                for (int c = 0; c < 4; c++) acc[mi][nf][c] = 0.f;

        // ---- prologue: stage 0 into buffer 0 ----
        {
            float4 ar[4];
#pragma unroll
            for (int i = 0; i < 4; i++)
                ar[i] = *reinterpret_cast<const float4*>(
                    keys + (size_t)(row0 + amRow[i]) * DDIM + 0 + amQ * 4);
#pragma unroll
            for (int i = 0; i < 4; i++) {
                int idx = tid + i * THREADS;
                int h = idx >> 3, c = idx & 7;
                cp_async16(sb + OFF_B + swz128((uint32_t)(h * 128 + c * 16)),
                           g_wt + (size_t)(n0 + h) * DDIM + 0 + c * 8);
            }
            CP_COMMIT();
#pragma unroll
            for (int i = 0; i < 4; i++) {
                union { __half2 hh2[2]; uint2 u; } cv;
                cv.hh2[0] = __floats2half2_rn(ar[i].x, ar[i].y);
                cv.hh2[1] = __floats2half2_rn(ar[i].z, ar[i].w);
                *reinterpret_cast<uint2*>(smem + OFF_A +
                    swz128((uint32_t)(amRow[i] * 128 + amQ * 8))) = cv.u;
            }
            CP_WAIT0();
            __syncthreads();
        }

#pragma unroll 1
        for (int ks = 0; ks < K_STEPS; ks += 2) {
            STAGE(0, ks, true);
            STAGE(1, ks + 1, (ks + 2) < K_STEPS);
        }

        // ---- fused epilogue for this h-chunk ----
        const int t2 = (lane & 3) * 2;
#pragma unroll
        for (int mi = 0; mi < 4; mi++) {
#pragma unroll
            for (int nf = 0; nf < 4; nf++) {
                const int n = n0 + warp_n * 32 + nf * 8 + t2;
                const float q0 = s_q[n],  q1 = s_q[n + 1];
                const float w0 = s_wv[n], w1 = s_wv[n + 1];
                sc[mi*2]     = fmaf(fast_tanh(acc[mi][nf][0] + q0), w0, sc[mi*2]);
                sc[mi*2]     = fmaf(fast_tanh(acc[mi][nf][1] + q1), w1, sc[mi*2]);
                sc[mi*2 + 1] = fmaf(fast_tanh(acc[mi][nf][2] + q0), w0, sc[mi*2+1]);
                sc[mi*2 + 1] = fmaf(fast_tanh(acc[mi][nf][3] + q1), w1, sc[mi*2+1]);
            }
        }
    }

    // ---- reduce scores ----
#pragma unroll
    for (int i = 0; i < 8; i++) {
        sc[i] += __shfl_xor_sync(0xFFFFFFFFu, sc[i], 1);
        sc[i] += __shfl_xor_sync(0xFFFFFFFFu, sc[i], 2);
    }
    __syncthreads();   // s_out reuse safe
    if ((lane & 3) == 0 && (warp_n & 1) == 0) {
        const int g = lane >> 2;
        const int grp = warp_n >> 1;
        float* slot = s_out + grp * M_TILE;
#pragma unroll
        for (int mi = 0; mi < 4; mi++) {
            const int r0 = warp_m * 64 + mi * 16 + g;
            slot[r0]     = sc[mi*2];
            slot[r0 + 8] = sc[mi*2 + 1];
        }
    }
    __syncthreads();
    if ((lane & 3) == 0 && (warp_n & 1) == 1) {
        const int g = lane >> 2;
        const int grp = warp_n >> 1;
        float* slot = s_out + grp * M_TILE;
#pragma unroll
        for (int mi = 0; mi < 4; mi++) {
            const int r0 = warp_m * 64 + mi * 16 + g;
            slot[r0]     += sc[mi*2];
            slot[r0 + 8] += sc[mi*2 + 1];
        }
    }
    __syncthreads();
    if (tid < M_TILE) {
        float v = s_out[tid] + s_out[M_TILE + tid] +
                  s_out[2 * M_TILE + tid] + s_out[3 * M_TILE + tid];
        out[row0 + tid] = v;
    }
}

// ============================ launch ======================================
extern "C" void kernel_launch(void* const* d_in, const int* in_sizes, int n_in,
                              void* d_out, int out_size) {
    const float* queries = (const float*)d_in[0];
    const float* keys    = (const float*)d_in[1];
    const float* W_q     = (const float*)d_in[2];
    const float* W_k     = (const float*)d_in[3];
    const float* w_v     = (const float*)d_in[4];
    float* out = (float*)d_out;

    cudaFuncSetAttribute(attn_main_kernel,
                         cudaFuncAttributeMaxDynamicSharedMemorySize, SMEM_TOTAL);

    prep_kernel<<<WCONV_BLOCKS + QPROJ_BLOCKS, 256>>>(W_k, queries, W_q);
    attn_main_kernel<<<NUM_TILES, THREADS, SMEM_TOTAL>>>(keys, w_v, out);
}

// round 7
// speedup vs baseline: 1.0700x; 1.0700x over previous
#include <cuda_runtime.h>
#include <cuda_fp16.h>
#include <cstdint>

// ============================ problem constants ============================
namespace {
constexpr int B_SZ  = 16;
constexpr int LKDIM = 8192;
constexpr int DDIM  = 1024;
constexpr int HDIM  = 1024;
constexpr int BL    = B_SZ * LKDIM;          // 131072 GEMM rows

constexpr int M_TILE  = 128;
constexpr int N_TILE  = 256;                 // h-chunk per pass
constexpr int PASSES  = HDIM / N_TILE;       // 4
constexpr int K_HALF  = 64;                  // halves per K stage (128B rows)
constexpr int K_STEPS = DDIM / K_HALF;       // 16
constexpr int THREADS = 512;                 // 16 warps: 2(M) x 8(N)
constexpr int NUM_TILES = BL / M_TILE;       // 1024 CTAs

constexpr int A_BYTES = M_TILE * 128;        // 16 KB / stage
constexpr int B_BYTES = N_TILE * 128;        // 32 KB / stage

// dynamic SMEM layout
constexpr int OFF_Q   = 0;                       // 1024 f32
constexpr int OFF_WV  = OFF_Q  + HDIM * 4;       // 1024 f32
constexpr int OFF_OUT = OFF_WV + HDIM * 4;       // 128*4 f32 partial slots
constexpr int OFF_A   = 10240;                   // 1024-aligned
constexpr int OFF_B   = OFF_A + 2 * A_BYTES;     // +32KB
constexpr int SMEM_TOTAL = OFF_B + 2 * B_BYTES;  // 108544 B

// prep kernel split
constexpr int WCONV_BLOCKS = (HDIM * DDIM) / 256;   // 4096
constexpr int QPROJ_BLOCKS = B_SZ * 4;              // 64
} // namespace

// ============================ device scratch ==============================
__device__ float  g_q [B_SZ * HDIM];   // projected queries (fp32, exact)
__device__ __half g_wt[HDIM * DDIM];   // W_k^T: [h][d] fp16

// ============================ helpers =====================================
__device__ __forceinline__ uint32_t smem_u32(const void* p) {
    uint32_t a;
    asm("{ .reg .u64 t; cvta.to.shared.u64 t, %1; cvt.u32.u64 %0, t; }"
        : "=r"(a) : "l"(p));
    return a;
}
__device__ __forceinline__ uint32_t swz128(uint32_t off) {
    return off ^ ((off >> 3) & 0x70);
}
__device__ __forceinline__ void ldm_x4(uint32_t& r0, uint32_t& r1,
                                       uint32_t& r2, uint32_t& r3, uint32_t addr) {
    asm volatile("ldmatrix.sync.aligned.m8n8.x4.shared.b16 {%0,%1,%2,%3}, [%4];"
                 : "=r"(r0), "=r"(r1), "=r"(r2), "=r"(r3) : "r"(addr));
}
__device__ __forceinline__ void mma16816(float* c, const uint32_t* a, const uint32_t* b) {
    asm volatile(
        "mma.sync.aligned.m16n8k16.row.col.f32.f16.f16.f32 "
        "{%0,%1,%2,%3}, {%4,%5,%6,%7}, {%8,%9}, {%0,%1,%2,%3};"
        : "+f"(c[0]), "+f"(c[1]), "+f"(c[2]), "+f"(c[3])
        : "r"(a[0]), "r"(a[1]), "r"(a[2]), "r"(a[3]), "r"(b[0]), "r"(b[1]));
}
__device__ __forceinline__ void cp_async16(uint32_t saddr, const void* gaddr) {
    asm volatile("cp.async.cg.shared.global [%0], [%1], 16;"
                 :: "r"(saddr), "l"(gaddr) : "memory");
}
#define CP_COMMIT() asm volatile("cp.async.commit_group;" ::: "memory")
#define CP_WAIT0()  asm volatile("cp.async.wait_group 0;"  ::: "memory")
#define STS64(addr, vx, vy) \
    asm volatile("st.shared.v2.u32 [%0], {%1,%2};" \
                 :: "r"(addr), "r"(vx), "r"(vy) : "memory")

__device__ __forceinline__ float fast_tanh(float x) {
    float r;
    asm("tanh.approx.f32 %0, %1;" : "=f"(r) : "f"(x));
    return r;
}

__device__ __forceinline__ void mma_all(float acc[4][4][4],
                                        uint32_t a[4][4], uint32_t bb[4][2])
{
#pragma unroll
    for (int mi = 0; mi < 4; mi++)
#pragma unroll
        for (int nf = 0; nf < 4; nf++)
            mma16816(acc[mi][nf], a[mi], bb[nf]);
}

// ============================ prep kernel (merged) =========================
__global__ void prep_kernel(const float* __restrict__ W_k,
                            const float* __restrict__ queries,
                            const float* __restrict__ W_q) {
    if (blockIdx.x < WCONV_BLOCKS) {
        int idx = blockIdx.x * 256 + threadIdx.x;   // over D*H
        int d = idx >> 10, h = idx & 1023;
        g_wt[(size_t)h * DDIM + d] = __float2half_rn(W_k[idx]);
    } else {
        const int qb = blockIdx.x - WCONV_BLOCKS;   // 0..63
        const int b  = qb >> 2;
        const int h0 = (qb & 3) * 256;
        __shared__ float sq[DDIM];
        for (int i = threadIdx.x; i < 256; i += 256) {}  // no-op keep shape
        for (int i = threadIdx.x; i < DDIM; i += 256)
            sq[i] = queries[b * DDIM + i];
        __syncthreads();
        const int h = h0 + threadIdx.x;
        float acc = 0.f;
        const float* w = W_q + h;
#pragma unroll 8
        for (int d = 0; d < DDIM; d++)
            acc = fmaf(sq[d], w[(size_t)d * HDIM], acc);
        g_q[b * HDIM + h] = acc;
    }
}

// ============================ main fused kernel ===========================
// One K-stage, compile-time buffer CUR. Single frag set (R4 proven register
// budget); all ldmatrix/STS addresses precomputed as base + small-constant.
#define STAGE(CUR, KIDX, HN)                                                  \
{                                                                             \
    const bool hn = (HN);                                                     \
    float4 ar[4];                                                             \
    if (hn) {                                                                 \
        const int k0n = ((KIDX) + 1) * K_HALF;                                \
        _Pragma("unroll")                                                     \
        for (int i = 0; i < 4; i++) {                                         \
            int idx = tid + i * THREADS;                                      \
            int hh = idx >> 3, c = idx & 7;                                   \
            cp_async16(sb + OFF_B + ((CUR) ^ 1) * B_BYTES +                   \
                           swz128((uint32_t)(hh * 128 + c * 16)),             \
                       g_wt + (size_t)(n0 + hh) * DDIM + k0n + c * 8);        \
        }                                                                     \
        CP_COMMIT();                                                          \
        _Pragma("unroll")                                                     \
        for (int i = 0; i < 4; i++)                                           \
            ar[i] = *reinterpret_cast<const float4*>(                         \
                keys + (size_t)(row0 + amRow[i]) * DDIM + k0n + amQ * 4);     \
    }                                                                         \
    _Pragma("unroll")                                                         \
    for (int kf = 0; kf < 4; kf++) {                                          \
        uint32_t a[4][4], bb[4][2];                                           \
        _Pragma("unroll")                                                     \
        for (int mi = 0; mi < 4; mi++)                                        \
            ldm_x4(a[mi][0], a[mi][1], a[mi][2], a[mi][3],                    \
                   aBase[mi] + ckA[kf] + (CUR) * A_BYTES);                    \
        _Pragma("unroll")                                                     \
        for (int p = 0; p < 2; p++)                                           \
            ldm_x4(bb[2*p][0], bb[2*p][1], bb[2*p+1][0], bb[2*p+1][1],        \
                   bBase[p] + ckB[kf] + (CUR) * B_BYTES);                     \
        mma_all(acc, a, bb);                                                  \
    }                                                                         \
    if (hn) {                                                                 \
        _Pragma("unroll")                                                     \
        for (int i = 0; i < 4; i++) {                                         \
            union { __half2 h2[2]; uint2 u; } cv;                             \
            cv.h2[0] = __floats2half2_rn(ar[i].x, ar[i].y);                   \
            cv.h2[1] = __floats2half2_rn(ar[i].z, ar[i].w);                   \
            STS64(stsA[i] + ((CUR) ^ 1) * A_BYTES, cv.u.x, cv.u.y);           \
        }                                                                     \
    }                                                                         \
    CP_WAIT0();                                                               \
    __syncthreads();                                                          \
}

__global__ void __launch_bounds__(THREADS, 1)
attn_main_kernel(const float* __restrict__ keys,
                 const float* __restrict__ w_v,
                 float* __restrict__ out) {
    extern __shared__ char smem[];
    const uint32_t sb  = smem_u32(smem);
    const int tid  = threadIdx.x;
    const int wid  = tid >> 5;
    const int lane = tid & 31;
    const int warp_m = wid >> 3;     // 0..1
    const int warp_n = wid & 7;      // 0..7
    const int row0 = blockIdx.x * M_TILE;
    const int b    = row0 >> 13;     // 8192 rows per batch

    float* s_q   = reinterpret_cast<float*>(smem + OFF_Q);
    float* s_wv  = reinterpret_cast<float*>(smem + OFF_WV);
    float* s_out = reinterpret_cast<float*>(smem + OFF_OUT);  // [4][128]

    for (int i = tid; i < HDIM; i += THREADS) {
        s_q[i]  = g_q[b * HDIM + i];
        s_wv[i] = w_v[i];
    }

    // lane-invariant fragment geometry
    const int rowA  = warp_m * 64 + (lane & 15);
    const int colA8 = (lane >> 4) << 3;
    const int gB    = lane >> 3;
    const int rowB  = warp_n * 32 + (lane & 7) + ((gB >> 1) << 3);
    const int colB8 = (gB & 1) << 3;

    // ---- precomputed ldmatrix addresses: base(row) + (col ^ s), s per-thread
    // swz128(row*128 + col) = row*128 + (col ^ ((row&7)<<4)) for col < 128,
    // and row&7 == lane&7 for every fragment of this thread.
    const uint32_t s7 = (uint32_t)((lane & 7) << 4);
    uint32_t aBase[4], bBase[2], ckA[4], ckB[4];
#pragma unroll
    for (int mi = 0; mi < 4; mi++)
        aBase[mi] = sb + OFF_A + (uint32_t)((rowA + mi * 16) * 128);
#pragma unroll
    for (int p = 0; p < 2; p++)
        bBase[p]  = sb + OFF_B + (uint32_t)((rowB + p * 16) * 128);
#pragma unroll
    for (int kf = 0; kf < 4; kf++) {
        ckA[kf] = ((uint32_t)((kf * 16 + colA8) * 2)) ^ s7;
        ckB[kf] = ((uint32_t)((kf * 16 + colB8) * 2)) ^ s7;
    }

    // A-loader indices + precomputed STS addresses (buffer 0)
    const int amRow [4] = { (tid + 0*THREADS) >> 4, (tid + 1*THREADS) >> 4,
                            (tid + 2*THREADS) >> 4, (tid + 3*THREADS) >> 4 };
    const int amQ = tid & 15;
    const uint32_t sSts = (uint32_t)(((tid >> 4) & 7) << 4);  // amRow[i]&7 invariant
    uint32_t stsA[4];
#pragma unroll
    for (int i = 0; i < 4; i++)
        stsA[i] = sb + OFF_A + (uint32_t)(amRow[i] * 128) +
                  (((uint32_t)(amQ * 8)) ^ sSts);

    float sc[8];
#pragma unroll
    for (int i = 0; i < 8; i++) sc[i] = 0.f;

    __syncthreads();   // publish s_q / s_wv

#pragma unroll 1
    for (int nc = 0; nc < PASSES; nc++) {
        const int n0 = nc * N_TILE;
        float acc[4][4][4];
#pragma unroll
        for (int mi = 0; mi < 4; mi++)
#pragma unroll
            for (int nf = 0; nf < 4; nf++)
#pragma unroll
                for (int c = 0; c < 4; c++) acc[mi][nf][c] = 0.f;

        // ---- prologue: stage 0 into buffer 0 ----
        {
            float4 ar[4];
#pragma unroll
            for (int i = 0; i < 4; i++)
                ar[i] = *reinterpret_cast<const float4*>(
                    keys + (size_t)(row0 + amRow[i]) * DDIM + 0 + amQ * 4);
#pragma unroll
            for (int i = 0; i < 4; i++) {
                int idx = tid + i * THREADS;
                int h = idx >> 3, c = idx & 7;
                cp_async16(sb + OFF_B + swz128((uint32_t)(h * 128 + c * 16)),
                           g_wt + (size_t)(n0 + h) * DDIM + 0 + c * 8);
            }
            CP_COMMIT();
#pragma unroll
            for (int i = 0; i < 4; i++) {
                union { __half2 h2[2]; uint2 u; } cv;
                cv.h2[0] = __floats2half2_rn(ar[i].x, ar[i].y);
                cv.h2[1] = __floats2half2_rn(ar[i].z, ar[i].w);
                STS64(stsA[i], cv.u.x, cv.u.y);
            }
            CP_WAIT0();
            __syncthreads();
        }

#pragma unroll 1
        for (int ks = 0; ks < K_STEPS; ks += 2) {
            STAGE(0, ks, true);
            STAGE(1, ks + 1, (ks + 2) < K_STEPS);
        }

        // ---- fused epilogue for this h-chunk ----
        const int t2 = (lane & 3) * 2;
#pragma unroll
        for (int mi = 0; mi < 4; mi++) {
#pragma unroll
            for (int nf = 0; nf < 4; nf++) {
                const int n = n0 + warp_n * 32 + nf * 8 + t2;
                const float q0 = s_q[n],  q1 = s_q[n + 1];
                const float w0 = s_wv[n], w1 = s_wv[n + 1];
                sc[mi*2]     = fmaf(fast_tanh(acc[mi][nf][0] + q0), w0, sc[mi*2]);
                sc[mi*2]     = fmaf(fast_tanh(acc[mi][nf][1] + q1), w1, sc[mi*2]);
                sc[mi*2 + 1] = fmaf(fast_tanh(acc[mi][nf][2] + q0), w0, sc[mi*2+1]);
                sc[mi*2 + 1] = fmaf(fast_tanh(acc[mi][nf][3] + q1), w1, sc[mi*2+1]);
            }
        }
    }

    // ---- reduce scores ----
#pragma unroll
    for (int i = 0; i < 8; i++) {
        sc[i] += __shfl_xor_sync(0xFFFFFFFFu, sc[i], 1);
        sc[i] += __shfl_xor_sync(0xFFFFFFFFu, sc[i], 2);
    }
    __syncthreads();   // s_out reuse safe
    if ((lane & 3) == 0 && (warp_n & 1) == 0) {
        const int g = lane >> 2;
        const int grp = warp_n >> 1;
        float* slot = s_out + grp * M_TILE;
#pragma unroll
        for (int mi = 0; mi < 4; mi++) {
            const int r0 = warp_m * 64 + mi * 16 + g;
            slot[r0]     = sc[mi*2];
            slot[r0 + 8] = sc[mi*2 + 1];
        }
    }
    __syncthreads();
    if ((lane & 3) == 0 && (warp_n & 1) == 1) {
        const int g = lane >> 2;
        const int grp = warp_n >> 1;
        float* slot = s_out + grp * M_TILE;
#pragma unroll
        for (int mi = 0; mi < 4; mi++) {
            const int r0 = warp_m * 64 + mi * 16 + g;
            slot[r0]     += sc[mi*2];
            slot[r0 + 8] += sc[mi*2 + 1];
        }
    }
    __syncthreads();
    if (tid < M_TILE) {
        float v = s_out[tid] + s_out[M_TILE + tid] +
                  s_out[2 * M_TILE + tid] + s_out[3 * M_TILE + tid];
        out[row0 + tid] = v;
    }
}

// ============================ launch ======================================
extern "C" void kernel_launch(void* const* d_in, const int* in_sizes, int n_in,
                              void* d_out, int out_size) {
    const float* queries = (const float*)d_in[0];
    const float* keys    = (const float*)d_in[1];
    const float* W_q     = (const float*)d_in[2];
    const float* W_k     = (const float*)d_in[3];
    const float* w_v     = (const float*)d_in[4];
    float* out = (float*)d_out;

    cudaFuncSetAttribute(attn_main_kernel,
                         cudaFuncAttributeMaxDynamicSharedMemorySize, SMEM_TOTAL);

    prep_kernel<<<WCONV_BLOCKS + QPROJ_BLOCKS, 256>>>(W_k, queries, W_q);
    attn_main_kernel<<<NUM_TILES, THREADS, SMEM_TOTAL>>>(keys, w_v, out);
}

// round 8
// speedup vs baseline: 1.1513x; 1.0759x over previous
#include <cuda_runtime.h>
#include <cuda_fp16.h>
#include <cstdint>

// ============================ problem constants ============================
namespace {
constexpr int B_SZ  = 16;
constexpr int LKDIM = 8192;
constexpr int DDIM  = 1024;
constexpr int HDIM  = 1024;
constexpr int BL    = B_SZ * LKDIM;          // 131072 GEMM rows

constexpr int M_TILE  = 64;
constexpr int N_TILE  = 256;                 // h-chunk per pass
constexpr int PASSES  = HDIM / N_TILE;       // 4
constexpr int K_HALF  = 64;                  // halves per K stage (128B rows)
constexpr int K_STEPS = DDIM / K_HALF;       // 16
constexpr int THREADS = 256;                 // 8 warps: 1(M) x 8(N)
constexpr int NUM_TILES = BL / M_TILE;       // 2048 CTAs

constexpr int A_BYTES = M_TILE * 128;        // 8 KB / stage
constexpr int B_BYTES = N_TILE * 128;        // 32 KB / stage

// dynamic SMEM layout (2 CTAs/SM must fit: 2 x 90 KB < 228 KB)
constexpr int OFF_Q   = 0;                       // 1024 f32
constexpr int OFF_WV  = OFF_Q  + HDIM * 4;       // 1024 f32
constexpr int OFF_OUT = OFF_WV + HDIM * 4;       // 64*4 f32 partial slots
constexpr int OFF_A   = 10240;                   // 1024-aligned
constexpr int OFF_B   = OFF_A + 2 * A_BYTES;     // 26624
constexpr int SMEM_TOTAL = OFF_B + 2 * B_BYTES;  // 92160 B

// prep kernels
constexpr int WCONV_BLOCKS = (HDIM * DDIM) / 256;   // 4096
constexpr int QPART_BLOCKS = B_SZ * 16;             // 16 b x 4 h x 4 d = 256
} // namespace

// ============================ device scratch ==============================
__device__ float  g_qp[4 * B_SZ * HDIM];  // q partials over 4 d-slices
__device__ float  g_q [B_SZ * HDIM];      // projected queries (fp32)
__device__ __half g_wt[HDIM * DDIM];      // W_k^T: [h][d] fp16

// ============================ helpers =====================================
__device__ __forceinline__ uint32_t smem_u32(const void* p) {
    uint32_t a;
    asm("{ .reg .u64 t; cvta.to.shared.u64 t, %1; cvt.u32.u64 %0, t; }"
        : "=r"(a) : "l"(p));
    return a;
}
__device__ __forceinline__ uint32_t swz128(uint32_t off) {
    return off ^ ((off >> 3) & 0x70);
}
__device__ __forceinline__ void ldm_x4(uint32_t& r0, uint32_t& r1,
                                       uint32_t& r2, uint32_t& r3, uint32_t addr) {
    asm volatile("ldmatrix.sync.aligned.m8n8.x4.shared.b16 {%0,%1,%2,%3}, [%4];"
                 : "=r"(r0), "=r"(r1), "=r"(r2), "=r"(r3) : "r"(addr));
}
__device__ __forceinline__ void mma16816(float* c, const uint32_t* a, const uint32_t* b) {
    asm volatile(
        "mma.sync.aligned.m16n8k16.row.col.f32.f16.f16.f32 "
        "{%0,%1,%2,%3}, {%4,%5,%6,%7}, {%8,%9}, {%0,%1,%2,%3};"
        : "+f"(c[0]), "+f"(c[1]), "+f"(c[2]), "+f"(c[3])
        : "r"(a[0]), "r"(a[1]), "r"(a[2]), "r"(a[3]), "r"(b[0]), "r"(b[1]));
}
__device__ __forceinline__ void cp_async16(uint32_t saddr, const void* gaddr) {
    asm volatile("cp.async.cg.shared.global [%0], [%1], 16;"
                 :: "r"(saddr), "l"(gaddr) : "memory");
}
#define CP_COMMIT() asm volatile("cp.async.commit_group;" ::: "memory")
#define CP_WAIT0()  asm volatile("cp.async.wait_group 0;"  ::: "memory")
#define STS64(addr, vx, vy) \
    asm volatile("st.shared.v2.u32 [%0], {%1,%2};" \
                 :: "r"(addr), "r"(vx), "r"(vy) : "memory")

__device__ __forceinline__ float fast_tanh(float x) {
    float r;
    asm("tanh.approx.f32 %0, %1;" : "=f"(r) : "f"(x));
    return r;
}

__device__ __forceinline__ void mma_all(float acc[4][4][4],
                                        uint32_t a[4][4], uint32_t bb[4][2])
{
#pragma unroll
    for (int mi = 0; mi < 4; mi++)
#pragma unroll
        for (int nf = 0; nf < 4; nf++)
            mma16816(acc[mi][nf], a[mi], bb[nf]);
}

// ============================ prep kernels ================================
// blocks [0, WCONV)        : W_k -> g_wt (transpose + fp16)
// blocks [WCONV, +QPART)   : q partials over 4 d-slices (no atomics)
__global__ void prep_kernel(const float* __restrict__ W_k,
                            const float* __restrict__ queries,
                            const float* __restrict__ W_q) {
    if (blockIdx.x < WCONV_BLOCKS) {
        int idx = blockIdx.x * 256 + threadIdx.x;   // over D*H
        int d = idx >> 10, h = idx & 1023;
        g_wt[(size_t)h * DDIM + d] = __float2half_rn(W_k[idx]);
    } else {
        const int qb  = blockIdx.x - WCONV_BLOCKS;  // 0..255
        const int b   = qb >> 4;                    // batch
        const int hc  = (qb >> 2) & 3;              // h-chunk (256)
        const int dc  = qb & 3;                     // d-slice (256)
        __shared__ float sq[256];
        sq[threadIdx.x] = queries[b * DDIM + dc * 256 + threadIdx.x];
        __syncthreads();
        const int h = hc * 256 + threadIdx.x;
        float acc = 0.f;
        const float* w = W_q + (size_t)(dc * 256) * HDIM + h;
#pragma unroll 8
        for (int d = 0; d < 256; d++)
            acc = fmaf(sq[d], w[(size_t)d * HDIM], acc);
        g_qp[(dc * B_SZ + b) * HDIM + h] = acc;
    }
}

__global__ void qcombine_kernel() {
    int i = blockIdx.x * 256 + threadIdx.x;   // over B_SZ*HDIM = 16384
    g_q[i] = (g_qp[i] + g_qp[B_SZ * HDIM + i]) +
             (g_qp[2 * B_SZ * HDIM + i] + g_qp[3 * B_SZ * HDIM + i]);
}

// ============================ main fused kernel ===========================
// One K-stage, compile-time buffer CUR. All ldmatrix/STS addresses
// precomputed as base + small-constant (R6 addressing).
#define STAGE(CUR, KIDX, HN)                                                  \
{                                                                             \
    const bool hn = (HN);                                                     \
    float4 ar[4];                                                             \
    if (hn) {                                                                 \
        const int k0n = ((KIDX) + 1) * K_HALF;                                \
        _Pragma("unroll")                                                     \
        for (int i = 0; i < 8; i++) {                                         \
            int idx = tid + i * THREADS;                                      \
            int hh = idx >> 3, c = idx & 7;                                   \
            cp_async16(sb + OFF_B + ((CUR) ^ 1) * B_BYTES +                   \
                           swz128((uint32_t)(hh * 128 + c * 16)),             \
                       g_wt + (size_t)(n0 + hh) * DDIM + k0n + c * 8);        \
        }                                                                     \
        CP_COMMIT();                                                          \
        _Pragma("unroll")                                                     \
        for (int i = 0; i < 4; i++)                                           \
            ar[i] = *reinterpret_cast<const float4*>(                         \
                keys + (size_t)(row0 + amRow[i]) * DDIM + k0n + amQ * 4);     \
    }                                                                         \
    _Pragma("unroll")                                                         \
    for (int kf = 0; kf < 4; kf++) {                                          \
        uint32_t a[4][4], bb[4][2];                                           \
        _Pragma("unroll")                                                     \
        for (int mi = 0; mi < 4; mi++)                                        \
            ldm_x4(a[mi][0], a[mi][1], a[mi][2], a[mi][3],                    \
                   aBase[mi] + ckA[kf] + (CUR) * A_BYTES);                    \
        _Pragma("unroll")                                                     \
        for (int p = 0; p < 2; p++)                                           \
            ldm_x4(bb[2*p][0], bb[2*p][1], bb[2*p+1][0], bb[2*p+1][1],        \
                   bBase[p] + ckB[kf] + (CUR) * B_BYTES);                     \
        mma_all(acc, a, bb);                                                  \
    }                                                                         \
    if (hn) {                                                                 \
        _Pragma("unroll")                                                     \
        for (int i = 0; i < 4; i++) {                                         \
            union { __half2 h2[2]; uint2 u; } cv;                             \
            cv.h2[0] = __floats2half2_rn(ar[i].x, ar[i].y);                   \
            cv.h2[1] = __floats2half2_rn(ar[i].z, ar[i].w);                   \
            STS64(stsA[i] + ((CUR) ^ 1) * A_BYTES, cv.u.x, cv.u.y);           \
        }                                                                     \
    }                                                                         \
    CP_WAIT0();                                                               \
    __syncthreads();                                                          \
}

__global__ void __launch_bounds__(THREADS, 2)
attn_main_kernel(const float* __restrict__ keys,
                 const float* __restrict__ w_v,
                 float* __restrict__ out) {
    extern __shared__ char smem[];
    const uint32_t sb  = smem_u32(smem);
    const int tid  = threadIdx.x;
    const int wid  = tid >> 5;       // 0..7 == warp_n
    const int lane = tid & 31;
    const int row0 = blockIdx.x * M_TILE;
    const int b    = row0 >> 13;     // 8192 rows per batch

    float* s_q   = reinterpret_cast<float*>(smem + OFF_Q);
    float* s_wv  = reinterpret_cast<float*>(smem + OFF_WV);
    float* s_out = reinterpret_cast<float*>(smem + OFF_OUT);  // [4][64]

    for (int i = tid; i < HDIM; i += THREADS) {
        s_q[i]  = g_q[b * HDIM + i];
        s_wv[i] = w_v[i];
    }

    // lane-invariant fragment geometry (single M warp-group)
    const int rowA  = lane & 15;
    const int colA8 = (lane >> 4) << 3;
    const int gB    = lane >> 3;
    const int rowB  = wid * 32 + (lane & 7) + ((gB >> 1) << 3);
    const int colB8 = (gB & 1) << 3;

    // precomputed ldmatrix addresses: swz128(row*128+col) = row*128 +
    // (col ^ ((row&7)<<4)), and row&7 == lane&7 for all frags of this thread.
    const uint32_t s7 = (uint32_t)((lane & 7) << 4);
    uint32_t aBase[4], bBase[2], ckA[4], ckB[4];
#pragma unroll
    for (int mi = 0; mi < 4; mi++)
        aBase[mi] = sb + OFF_A + (uint32_t)((rowA + mi * 16) * 128);
#pragma unroll
    for (int p = 0; p < 2; p++)
        bBase[p]  = sb + OFF_B + (uint32_t)((rowB + p * 16) * 128);
#pragma unroll
    for (int kf = 0; kf < 4; kf++) {
        ckA[kf] = ((uint32_t)((kf * 16 + colA8) * 2)) ^ s7;
        ckB[kf] = ((uint32_t)((kf * 16 + colB8) * 2)) ^ s7;
    }

    // A-loader: 4 x float4 per thread per stage (64 rows x 16 float4)
    const int amRow [4] = { (tid + 0*THREADS) >> 4, (tid + 1*THREADS) >> 4,
                            (tid + 2*THREADS) >> 4, (tid + 3*THREADS) >> 4 };
    const int amQ = tid & 15;
    const uint32_t sSts = (uint32_t)(((tid >> 4) & 7) << 4);
    uint32_t stsA[4];
#pragma unroll
    for (int i = 0; i < 4; i++)
        stsA[i] = sb + OFF_A + (uint32_t)(amRow[i] * 128) +
                  (((uint32_t)(amQ * 8)) ^ sSts);

    float sc[8];
#pragma unroll
    for (int i = 0; i < 8; i++) sc[i] = 0.f;

    __syncthreads();   // publish s_q / s_wv

#pragma unroll 1
    for (int nc = 0; nc < PASSES; nc++) {
        const int n0 = nc * N_TILE;
        float acc[4][4][4];
#pragma unroll
        for (int mi = 0; mi < 4; mi++)
#pragma unroll
            for (int nf = 0; nf < 4; nf++)
#pragma unroll
                for (int c = 0; c < 4; c++) acc[mi][nf][c] = 0.f;

        // ---- prologue: stage 0 into buffer 0 ----
        {
            float4 ar[4];
#pragma unroll
            for (int i = 0; i < 4; i++)
                ar[i] = *reinterpret_cast<const float4*>(
                    keys + (size_t)(row0 + amRow[i]) * DDIM + 0 + amQ * 4);
#pragma unroll
            for (int i = 0; i < 8; i++) {
                int idx = tid + i * THREADS;
                int h = idx >> 3, c = idx & 7;
                cp_async16(sb + OFF_B + swz128((uint32_t)(h * 128 + c * 16)),
                           g_wt + (size_t)(n0 + h) * DDIM + 0 + c * 8);
            }
            CP_COMMIT();
#pragma unroll
            for (int i = 0; i < 4; i++) {
                union { __half2 h2[2]; uint2 u; } cv;
                cv.h2[0] = __floats2half2_rn(ar[i].x, ar[i].y);
                cv.h2[1] = __floats2half2_rn(ar[i].z, ar[i].w);
                STS64(stsA[i], cv.u.x, cv.u.y);
            }
            CP_WAIT0();
            __syncthreads();
        }

#pragma unroll 1
        for (int ks = 0; ks < K_STEPS; ks += 2) {
            STAGE(0, ks, true);
            STAGE(1, ks + 1, (ks + 2) < K_STEPS);
        }

        // ---- fused epilogue for this h-chunk ----
        const int t2 = (lane & 3) * 2;
#pragma unroll
        for (int mi = 0; mi < 4; mi++) {
#pragma unroll
            for (int nf = 0; nf < 4; nf++) {
                const int n = n0 + wid * 32 + nf * 8 + t2;
                const float q0 = s_q[n],  q1 = s_q[n + 1];
                const float w0 = s_wv[n], w1 = s_wv[n + 1];
                sc[mi*2]     = fmaf(fast_tanh(acc[mi][nf][0] + q0), w0, sc[mi*2]);
                sc[mi*2]     = fmaf(fast_tanh(acc[mi][nf][1] + q1), w1, sc[mi*2]);
                sc[mi*2 + 1] = fmaf(fast_tanh(acc[mi][nf][2] + q0), w0, sc[mi*2+1]);
                sc[mi*2 + 1] = fmaf(fast_tanh(acc[mi][nf][3] + q1), w1, sc[mi*2+1]);
            }
        }
    }

    // ---- reduce scores ----
#pragma unroll
    for (int i = 0; i < 8; i++) {
        sc[i] += __shfl_xor_sync(0xFFFFFFFFu, sc[i], 1);
        sc[i] += __shfl_xor_sync(0xFFFFFFFFu, sc[i], 2);
    }
    __syncthreads();   // s_out reuse safe
    if ((lane & 3) == 0 && (wid & 1) == 0) {
        const int g = lane >> 2;
        float* slot = s_out + (wid >> 1) * M_TILE;
#pragma unroll
        for (int mi = 0; mi < 4; mi++) {
            const int r0 = mi * 16 + g;
            slot[r0]     = sc[mi*2];
            slot[r0 + 8] = sc[mi*2 + 1];
        }
    }
    __syncthreads();
    if ((lane & 3) == 0 && (wid & 1) == 1) {
        const int g = lane >> 2;
        float* slot = s_out + (wid >> 1) * M_TILE;
#pragma unroll
        for (int mi = 0; mi < 4; mi++) {
            const int r0 = mi * 16 + g;
            slot[r0]     += sc[mi*2];
            slot[r0 + 8] += sc[mi*2 + 1];
        }
    }
    __syncthreads();
    if (tid < M_TILE) {
        float v = (s_out[tid] + s_out[M_TILE + tid]) +
                  (s_out[2 * M_TILE + tid] + s_out[3 * M_TILE + tid]);
        out[row0 + tid] = v;
    }
}

// ============================ launch ======================================
extern "C" void kernel_launch(void* const* d_in, const int* in_sizes, int n_in,
                              void* d_out, int out_size) {
    const float* queries = (const float*)d_in[0];
    const float* keys    = (const float*)d_in[1];
    const float* W_q     = (const float*)d_in[2];
    const float* W_k     = (const float*)d_in[3];
    const float* w_v     = (const float*)d_in[4];
    float* out = (float*)d_out;

    cudaFuncSetAttribute(attn_main_kernel,
                         cudaFuncAttributeMaxDynamicSharedMemorySize, SMEM_TOTAL);

    prep_kernel<<<WCONV_BLOCKS + QPART_BLOCKS, 256>>>(W_k, queries, W_q);
    qcombine_kernel<<<(B_SZ * HDIM) / 256, 256>>>();
    attn_main_kernel<<<NUM_TILES, THREADS, SMEM_TOTAL>>>(keys, w_v, out);
}

// round 9
// speedup vs baseline: 1.2028x; 1.0447x over previous
#include <cuda_runtime.h>
#include <cuda_fp16.h>
#include <cstdint>

// ============================ problem constants ============================
namespace {
constexpr int B_SZ  = 16;
constexpr int LKDIM = 8192;
constexpr int DDIM  = 1024;
constexpr int HDIM  = 1024;
constexpr int BL    = B_SZ * LKDIM;          // 131072 GEMM rows

constexpr int M_TILE  = 128;
constexpr int N_TILE  = 256;                 // h-chunk per pass
constexpr int PASSES  = HDIM / N_TILE;       // 4
constexpr int K_HALF  = 64;                  // halves per K stage (128B rows)
constexpr int K_STEPS = DDIM / K_HALF;       // 16
constexpr int THREADS = 512;                 // 16 warps: 2(M) x 8(N)
constexpr int NUM_TILES = BL / M_TILE;       // 1024 CTAs

constexpr int A_BYTES = M_TILE * 128;        // 16 KB / stage
constexpr int B_BYTES = N_TILE * 128;        // 32 KB / stage

// dynamic SMEM layout: 3-stage pipeline
constexpr int OFF_Q   = 0;                       // 1024 f32
constexpr int OFF_WV  = OFF_Q  + HDIM * 4;       // 1024 f32
constexpr int OFF_OUT = OFF_WV + HDIM * 4;       // 128*4 f32 partial slots
constexpr int OFF_A   = 10240;                   // 1024-aligned, 3 bufs
constexpr int OFF_B   = OFF_A + 3 * A_BYTES;     // 59392
constexpr int SMEM_TOTAL = OFF_B + 3 * B_BYTES;  // 157696 B (1 CTA/SM)

// prep kernels
constexpr int WCONV_BLOCKS = (HDIM * DDIM) / 256;   // 4096
constexpr int QPART_BLOCKS = B_SZ * 16;             // 256
} // namespace

// ============================ device scratch ==============================
__device__ float  g_qp[4 * B_SZ * HDIM];  // q partials over 4 d-slices
__device__ float  g_q [B_SZ * HDIM];      // projected queries (fp32)
__device__ __half g_wt[HDIM * DDIM];      // W_k^T: [h][d] fp16

// ============================ helpers =====================================
__device__ __forceinline__ uint32_t smem_u32(const void* p) {
    uint32_t a;
    asm("{ .reg .u64 t; cvta.to.shared.u64 t, %1; cvt.u32.u64 %0, t; }"
        : "=r"(a) : "l"(p));
    return a;
}
__device__ __forceinline__ uint32_t swz128(uint32_t off) {
    return off ^ ((off >> 3) & 0x70);
}
__device__ __forceinline__ void ldm_x4(uint32_t& r0, uint32_t& r1,
                                       uint32_t& r2, uint32_t& r3, uint32_t addr) {
    asm volatile("ldmatrix.sync.aligned.m8n8.x4.shared.b16 {%0,%1,%2,%3}, [%4];"
                 : "=r"(r0), "=r"(r1), "=r"(r2), "=r"(r3) : "r"(addr));
}
__device__ __forceinline__ void mma16816(float* c, const uint32_t* a, const uint32_t* b) {
    asm volatile(
        "mma.sync.aligned.m16n8k16.row.col.f32.f16.f16.f32 "
        "{%0,%1,%2,%3}, {%4,%5,%6,%7}, {%8,%9}, {%0,%1,%2,%3};"
        : "+f"(c[0]), "+f"(c[1]), "+f"(c[2]), "+f"(c[3])
        : "r"(a[0]), "r"(a[1]), "r"(a[2]), "r"(a[3]), "r"(b[0]), "r"(b[1]));
}
__device__ __forceinline__ void cp_async16(uint32_t saddr, const void* gaddr) {
    asm volatile("cp.async.cg.shared.global [%0], [%1], 16;"
                 :: "r"(saddr), "l"(gaddr) : "memory");
}
#define CP_COMMIT() asm volatile("cp.async.commit_group;" ::: "memory")
#define DO_WAIT_1() asm volatile("cp.async.wait_group 1;" ::: "memory")
#define DO_WAIT_0() asm volatile("cp.async.wait_group 0;" ::: "memory")
#define DO_WAIT_9()
#define STS64(addr, vx, vy) \
    asm volatile("st.shared.v2.u32 [%0], {%1,%2};" \
                 :: "r"(addr), "r"(vx), "r"(vy) : "memory")

__device__ __forceinline__ float fast_tanh(float x) {
    float r;
    asm("tanh.approx.f32 %0, %1;" : "=f"(r) : "f"(x));
    return r;
}

__device__ __forceinline__ void mma_all(float acc[4][4][4],
                                        uint32_t a[4][4], uint32_t bb[4][2])
{
#pragma unroll
    for (int mi = 0; mi < 4; mi++)
#pragma unroll
        for (int nf = 0; nf < 4; nf++)
            mma16816(acc[mi][nf], a[mi], bb[nf]);
}

// ============================ prep kernels ================================
__global__ void prep_kernel(const float* __restrict__ W_k,
                            const float* __restrict__ queries,
                            const float* __restrict__ W_q) {
    if (blockIdx.x < WCONV_BLOCKS) {
        int idx = blockIdx.x * 256 + threadIdx.x;   // over D*H
        int d = idx >> 10, h = idx & 1023;
        g_wt[(size_t)h * DDIM + d] = __float2half_rn(W_k[idx]);
    } else {
        const int qb  = blockIdx.x - WCONV_BLOCKS;  // 0..255
        const int b   = qb >> 4;
        const int hc  = (qb >> 2) & 3;
        const int dc  = qb & 3;
        __shared__ float sq[256];
        sq[threadIdx.x] = queries[b * DDIM + dc * 256 + threadIdx.x];
        __syncthreads();
        const int h = hc * 256 + threadIdx.x;
        float acc = 0.f;
        const float* w = W_q + (size_t)(dc * 256) * HDIM + h;
#pragma unroll 8
        for (int d = 0; d < 256; d++)
            acc = fmaf(sq[d], w[(size_t)d * HDIM], acc);
        g_qp[(dc * B_SZ + b) * HDIM + h] = acc;
    }
}

__global__ void qcombine_kernel() {
    int i = blockIdx.x * 256 + threadIdx.x;
    g_q[i] = (g_qp[i] + g_qp[B_SZ * HDIM + i]) +
             (g_qp[2 * B_SZ * HDIM + i] + g_qp[3 * B_SZ * HDIM + i]);
}

// ============================ main fused kernel ===========================
// 3-stage pipeline. Stage KIDX computes buffer CUR = KIDX%3.
//  - commits B loads for stage KIDX+2 into buffer (CUR+2)%3
//  - LDGs A for stage KIDX+1, STS into buffer (CUR+1)%3 after compute
//  - wait W: 1 for stages <=13 (frees group KIDX+1), 0 for stage 14, none 15
#define STAGE(CUR, KIDX, W)                                                   \
{                                                                             \
    const bool hn2 = ((KIDX) + 2 < K_STEPS);                                  \
    const bool hn1 = ((KIDX) + 1 < K_STEPS);                                  \
    float4 ar[4];                                                             \
    if (hn2) {                                                                \
        const int k0n = ((KIDX) + 2) * K_HALF;                                \
        _Pragma("unroll")                                                     \
        for (int i = 0; i < 4; i++) {                                         \
            int idx = tid + i * THREADS;                                      \
            int hh = idx >> 3, c = idx & 7;                                   \
            cp_async16(sb + OFF_B + (((CUR) + 2) % 3) * B_BYTES +             \
                           swz128((uint32_t)(hh * 128 + c * 16)),             \
                       g_wt + (size_t)(n0 + hh) * DDIM + k0n + c * 8);        \
        }                                                                     \
        CP_COMMIT();                                                          \
    }                                                                         \
    if (hn1) {                                                                \
        const int k0a = ((KIDX) + 1) * K_HALF;                                \
        _Pragma("unroll")                                                     \
        for (int i = 0; i < 4; i++)                                           \
            ar[i] = *reinterpret_cast<const float4*>(                         \
                keys + (size_t)(row0 + amRow[i]) * DDIM + k0a + amQ * 4);     \
    }                                                                         \
    _Pragma("unroll")                                                         \
    for (int kf = 0; kf < 4; kf++) {                                          \
        uint32_t a[4][4], bb[4][2];                                           \
        _Pragma("unroll")                                                     \
        for (int mi = 0; mi < 4; mi++)                                        \
            ldm_x4(a[mi][0], a[mi][1], a[mi][2], a[mi][3],                    \
                   aBase[mi] + ckA[kf] + (CUR) * A_BYTES);                    \
        _Pragma("unroll")                                                     \
        for (int p = 0; p < 2; p++)                                           \
            ldm_x4(bb[2*p][0], bb[2*p][1], bb[2*p+1][0], bb[2*p+1][1],        \
                   bBase[p] + ckB[kf] + (CUR) * B_BYTES);                     \
        mma_all(acc, a, bb);                                                  \
    }                                                                         \
    if (hn1) {                                                                \
        _Pragma("unroll")                                                     \
        for (int i = 0; i < 4; i++) {                                         \
            union { __half2 h2[2]; uint2 u; } cv;                             \
            cv.h2[0] = __floats2half2_rn(ar[i].x, ar[i].y);                   \
            cv.h2[1] = __floats2half2_rn(ar[i].z, ar[i].w);                   \
            STS64(stsA[i] + (((CUR) + 1) % 3) * A_BYTES, cv.u.x, cv.u.y);     \
        }                                                                     \
    }                                                                         \
    DO_WAIT_##W();                                                            \
    __syncthreads();                                                          \
}

__global__ void __launch_bounds__(THREADS, 1)
attn_main_kernel(const float* __restrict__ keys,
                 const float* __restrict__ w_v,
                 float* __restrict__ out) {
    extern __shared__ char smem[];
    const uint32_t sb  = smem_u32(smem);
    const int tid  = threadIdx.x;
    const int wid  = tid >> 5;
    const int lane = tid & 31;
    const int warp_m = wid >> 3;     // 0..1
    const int warp_n = wid & 7;      // 0..7
    const int row0 = blockIdx.x * M_TILE;
    const int b    = row0 >> 13;     // 8192 rows per batch

    float* s_q   = reinterpret_cast<float*>(smem + OFF_Q);
    float* s_wv  = reinterpret_cast<float*>(smem + OFF_WV);
    float* s_out = reinterpret_cast<float*>(smem + OFF_OUT);  // [4][128]

    for (int i = tid; i < HDIM; i += THREADS) {
        s_q[i]  = g_q[b * HDIM + i];
        s_wv[i] = w_v[i];
    }

    // lane-invariant fragment geometry
    const int rowA  = warp_m * 64 + (lane & 15);
    const int colA8 = (lane >> 4) << 3;
    const int gB    = lane >> 3;
    const int rowB  = warp_n * 32 + (lane & 7) + ((gB >> 1) << 3);
    const int colB8 = (gB & 1) << 3;

    // precomputed ldmatrix addresses (swz identity, row&7 == lane&7)
    const uint32_t s7 = (uint32_t)((lane & 7) << 4);
    uint32_t aBase[4], bBase[2], ckA[4], ckB[4];
#pragma unroll
    for (int mi = 0; mi < 4; mi++)
        aBase[mi] = sb + OFF_A + (uint32_t)((rowA + mi * 16) * 128);
#pragma unroll
    for (int p = 0; p < 2; p++)
        bBase[p]  = sb + OFF_B + (uint32_t)((rowB + p * 16) * 128);
#pragma unroll
    for (int kf = 0; kf < 4; kf++) {
        ckA[kf] = ((uint32_t)((kf * 16 + colA8) * 2)) ^ s7;
        ckB[kf] = ((uint32_t)((kf * 16 + colB8) * 2)) ^ s7;
    }

    // A-loader: 4 x float4 per thread per stage
    const int amRow [4] = { (tid + 0*THREADS) >> 4, (tid + 1*THREADS) >> 4,
                            (tid + 2*THREADS) >> 4, (tid + 3*THREADS) >> 4 };
    const int amQ = tid & 15;
    const uint32_t sSts = (uint32_t)(((tid >> 4) & 7) << 4);
    uint32_t stsA[4];
#pragma unroll
    for (int i = 0; i < 4; i++)
        stsA[i] = sb + OFF_A + (uint32_t)(amRow[i] * 128) +
                  (((uint32_t)(amQ * 8)) ^ sSts);

    float sc[8];
#pragma unroll
    for (int i = 0; i < 8; i++) sc[i] = 0.f;

    __syncthreads();   // publish s_q / s_wv

#pragma unroll 1
    for (int nc = 0; nc < PASSES; nc++) {
        const int n0 = nc * N_TILE;
        float acc[4][4][4];
#pragma unroll
        for (int mi = 0; mi < 4; mi++)
#pragma unroll
            for (int nf = 0; nf < 4; nf++)
#pragma unroll
                for (int c = 0; c < 4; c++) acc[mi][nf][c] = 0.f;

        // ---- prologue: B0 -> buf0, B1 -> buf1 (separate groups), A0 -> buf0
        {
#pragma unroll
            for (int s = 0; s < 2; s++) {
#pragma unroll
                for (int i = 0; i < 4; i++) {
                    int idx = tid + i * THREADS;
                    int h = idx >> 3, c = idx & 7;
                    cp_async16(sb + OFF_B + s * B_BYTES +
                                   swz128((uint32_t)(h * 128 + c * 16)),
                               g_wt + (size_t)(n0 + h) * DDIM + s * K_HALF + c * 8);
                }
                CP_COMMIT();
            }
            float4 ar[4];
#pragma unroll
            for (int i = 0; i < 4; i++)
                ar[i] = *reinterpret_cast<const float4*>(
                    keys + (size_t)(row0 + amRow[i]) * DDIM + 0 + amQ * 4);
#pragma unroll
            for (int i = 0; i < 4; i++) {
                union { __half2 h2[2]; uint2 u; } cv;
                cv.h2[0] = __floats2half2_rn(ar[i].x, ar[i].y);
                cv.h2[1] = __floats2half2_rn(ar[i].z, ar[i].w);
                STS64(stsA[i], cv.u.x, cv.u.y);
            }
            DO_WAIT_1();        // B0 complete; B1 may still fly
            __syncthreads();
        }

        // ---- 16 stages: 4 triples + 4 peeled with exact wait depths ----
#pragma unroll 1
        for (int ks = 0; ks < 12; ks += 3) {
            STAGE(0, ks,     1);
            STAGE(1, ks + 1, 1);
            STAGE(2, ks + 2, 1);
        }
        STAGE(0, 12, 1);
        STAGE(1, 13, 1);
        STAGE(2, 14, 0);
        STAGE(0, 15, 9);

        // ---- fused epilogue for this h-chunk ----
        const int t2 = (lane & 3) * 2;
#pragma unroll
        for (int mi = 0; mi < 4; mi++) {
#pragma unroll
            for (int nf = 0; nf < 4; nf++) {
                const int n = n0 + warp_n * 32 + nf * 8 + t2;
                const float q0 = s_q[n],  q1 = s_q[n + 1];
                const float w0 = s_wv[n], w1 = s_wv[n + 1];
                sc[mi*2]     = fmaf(fast_tanh(acc[mi][nf][0] + q0), w0, sc[mi*2]);
                sc[mi*2]     = fmaf(fast_tanh(acc[mi][nf][1] + q1), w1, sc[mi*2]);
                sc[mi*2 + 1] = fmaf(fast_tanh(acc[mi][nf][2] + q0), w0, sc[mi*2+1]);
                sc[mi*2 + 1] = fmaf(fast_tanh(acc[mi][nf][3] + q1), w1, sc[mi*2+1]);
            }
        }
    }

    // ---- reduce scores ----
#pragma unroll
    for (int i = 0; i < 8; i++) {
        sc[i] += __shfl_xor_sync(0xFFFFFFFFu, sc[i], 1);
        sc[i] += __shfl_xor_sync(0xFFFFFFFFu, sc[i], 2);
    }
    __syncthreads();
    if ((lane & 3) == 0 && (warp_n & 1) == 0) {
        const int g = lane >> 2;
        float* slot = s_out + (warp_n >> 1) * M_TILE;
#pragma unroll
        for (int mi = 0; mi < 4; mi++) {
            const int r0 = warp_m * 64 + mi * 16 + g;
            slot[r0]     = sc[mi*2];
            slot[r0 + 8] = sc[mi*2 + 1];
        }
    }
    __syncthreads();
    if ((lane & 3) == 0 && (warp_n & 1) == 1) {
        const int g = lane >> 2;
        float* slot = s_out + (warp_n >> 1) * M_TILE;
#pragma unroll
        for (int mi = 0; mi < 4; mi++) {
            const int r0 = warp_m * 64 + mi * 16 + g;
            slot[r0]     += sc[mi*2];
            slot[r0 + 8] += sc[mi*2 + 1];
        }
    }
    __syncthreads();
    if (tid < M_TILE) {
        float v = (s_out[tid] + s_out[M_TILE + tid]) +
                  (s_out[2 * M_TILE + tid] + s_out[3 * M_TILE + tid]);
        out[row0 + tid] = v;
    }
}

// ============================ launch ======================================
extern "C" void kernel_launch(void* const* d_in, const int* in_sizes, int n_in,
                              void* d_out, int out_size) {
    const float* queries = (const float*)d_in[0];
    const float* keys    = (const float*)d_in[1];
    const float* W_q     = (const float*)d_in[2];
    const float* W_k     = (const float*)d_in[3];
    const float* w_v     = (const float*)d_in[4];
    float* out = (float*)d_out;

    cudaFuncSetAttribute(attn_main_kernel,
                         cudaFuncAttributeMaxDynamicSharedMemorySize, SMEM_TOTAL);

    prep_kernel<<<WCONV_BLOCKS + QPART_BLOCKS, 256>>>(W_k, queries, W_q);
    qcombine_kernel<<<(B_SZ * HDIM) / 256, 256>>>();
    attn_main_kernel<<<NUM_TILES, THREADS, SMEM_TOTAL>>>(keys, w_v, out);
}

// round 10
// speedup vs baseline: 1.2078x; 1.0042x over previous
#include <cuda_runtime.h>
#include <cuda_fp16.h>
#include <cstdint>

// ============================ problem constants ============================
namespace {
constexpr int B_SZ  = 16;
constexpr int LKDIM = 8192;
constexpr int DDIM  = 1024;
constexpr int HDIM  = 1024;
constexpr int BL    = B_SZ * LKDIM;          // 131072 GEMM rows

constexpr int M_TILE  = 128;
constexpr int N_TILE  = 256;                 // h-chunk per pass
constexpr int PASSES  = HDIM / N_TILE;       // 4
constexpr int K_HALF  = 64;                  // halves per K stage (128B rows)
constexpr int K_STEPS = DDIM / K_HALF;       // 16
constexpr int THREADS = 512;                 // 16 warps: 2(M) x 8(N)
constexpr int NUM_TILES = BL / M_TILE;       // 1024 CTAs

constexpr int A_BYTES = M_TILE * 128;        // 16 KB / stage
constexpr int B_BYTES = N_TILE * 128;        // 32 KB / stage

// dynamic SMEM layout: 3-stage pipeline
constexpr int OFF_Q   = 0;                       // 1024 f32
constexpr int OFF_WV  = OFF_Q  + HDIM * 4;       // 1024 f32
constexpr int OFF_OUT = OFF_WV + HDIM * 4;       // 128*4 f32 partial slots
constexpr int OFF_A   = 10240;                   // 1024-aligned, 3 bufs
constexpr int OFF_B   = OFF_A + 3 * A_BYTES;     // 59392
constexpr int SMEM_TOTAL = OFF_B + 3 * B_BYTES;  // 157696 B (1 CTA/SM)

// prep kernels
constexpr int WCONV_BLOCKS = (HDIM * DDIM) / 256;   // 4096
constexpr int QPART_BLOCKS = B_SZ * 16;             // 256
} // namespace

// ============================ device scratch ==============================
__device__ float  g_qp[4 * B_SZ * HDIM];  // q partials over 4 d-slices
__device__ float  g_q [B_SZ * HDIM];      // projected queries (fp32)
__device__ __half g_wt[HDIM * DDIM];      // W_k^T: [h][d] fp16

// ============================ helpers =====================================
__device__ __forceinline__ uint32_t smem_u32(const void* p) {
    uint32_t a;
    asm("{ .reg .u64 t; cvta.to.shared.u64 t, %1; cvt.u32.u64 %0, t; }"
        : "=r"(a) : "l"(p));
    return a;
}
__device__ __forceinline__ uint32_t swz128(uint32_t off) {
    return off ^ ((off >> 3) & 0x70);
}
__device__ __forceinline__ void ldm_x4(uint32_t& r0, uint32_t& r1,
                                       uint32_t& r2, uint32_t& r3, uint32_t addr) {
    asm volatile("ldmatrix.sync.aligned.m8n8.x4.shared.b16 {%0,%1,%2,%3}, [%4];"
                 : "=r"(r0), "=r"(r1), "=r"(r2), "=r"(r3) : "r"(addr));
}
__device__ __forceinline__ void mma16816(float* c, const uint32_t* a, const uint32_t* b) {
    asm volatile(
        "mma.sync.aligned.m16n8k16.row.col.f32.f16.f16.f32 "
        "{%0,%1,%2,%3}, {%4,%5,%6,%7}, {%8,%9}, {%0,%1,%2,%3};"
        : "+f"(c[0]), "+f"(c[1]), "+f"(c[2]), "+f"(c[3])
        : "r"(a[0]), "r"(a[1]), "r"(a[2]), "r"(a[3]), "r"(b[0]), "r"(b[1]));
}
__device__ __forceinline__ void cp_async16(uint32_t saddr, const void* gaddr) {
    asm volatile("cp.async.cg.shared.global [%0], [%1], 16;"
                 :: "r"(saddr), "l"(gaddr) : "memory");
}
#define CP_COMMIT() asm volatile("cp.async.commit_group;" ::: "memory")
#define DO_WAIT_1() asm volatile("cp.async.wait_group 1;" ::: "memory")
#define DO_WAIT_0() asm volatile("cp.async.wait_group 0;" ::: "memory")
#define DO_WAIT_9()
#define STS64(addr, vx, vy) \
    asm volatile("st.shared.v2.u32 [%0], {%1,%2};" \
                 :: "r"(addr), "r"(vx), "r"(vy) : "memory")

__device__ __forceinline__ float fast_tanh(float x) {
    float r;
    asm("tanh.approx.f32 %0, %1;" : "=f"(r) : "f"(x));
    return r;
}

__device__ __forceinline__ void mma_all(float acc[4][4][4],
                                        uint32_t a[4][4], uint32_t bb[4][2])
{
#pragma unroll
    for (int mi = 0; mi < 4; mi++)
#pragma unroll
        for (int nf = 0; nf < 4; nf++)
            mma16816(acc[mi][nf], a[mi], bb[nf]);
}

// ============================ prep kernels ================================
__global__ void prep_kernel(const float* __restrict__ W_k,
                            const float* __restrict__ queries,
                            const float* __restrict__ W_q) {
    if (blockIdx.x < WCONV_BLOCKS) {
        int idx = blockIdx.x * 256 + threadIdx.x;   // over D*H
        int d = idx >> 10, h = idx & 1023;
        g_wt[(size_t)h * DDIM + d] = __float2half_rn(W_k[idx]);
    } else {
        const int qb  = blockIdx.x - WCONV_BLOCKS;  // 0..255
        const int b   = qb >> 4;
        const int hc  = (qb >> 2) & 3;
        const int dc  = qb & 3;
        __shared__ float sq[256];
        sq[threadIdx.x] = queries[b * DDIM + dc * 256 + threadIdx.x];
        __syncthreads();
        const int h = hc * 256 + threadIdx.x;
        float acc = 0.f;
        const float* w = W_q + (size_t)(dc * 256) * HDIM + h;
#pragma unroll 8
        for (int d = 0; d < 256; d++)
            acc = fmaf(sq[d], w[(size_t)d * HDIM], acc);
        g_qp[(dc * B_SZ + b) * HDIM + h] = acc;
    }
}

__global__ void qcombine_kernel() {
    int i = blockIdx.x * 256 + threadIdx.x;
    g_q[i] = (g_qp[i] + g_qp[B_SZ * HDIM + i]) +
             (g_qp[2 * B_SZ * HDIM + i] + g_qp[3 * B_SZ * HDIM + i]);
}

// ============================ main fused kernel ===========================
// 3-stage pipeline. Stage KIDX computes buffer CUR = KIDX%3.
//  - commits B loads for stage KIDX+2 into buffer (CUR+2)%3
//  - LDGs A for stage KIDX+1, STS into buffer (CUR+1)%3 after compute
//  - wait W: 1 for stages <=13 (frees group KIDX+1), 0 for stage 14, none 15
#define STAGE(CUR, KIDX, W)                                                   \
{                                                                             \
    const bool hn2 = ((KIDX) + 2 < K_STEPS);                                  \
    const bool hn1 = ((KIDX) + 1 < K_STEPS);                                  \
    float4 ar[4];                                                             \
    if (hn2) {                                                                \
        const int k0n = ((KIDX) + 2) * K_HALF;                                \
        _Pragma("unroll")                                                     \
        for (int i = 0; i < 4; i++) {                                         \
            int idx = tid + i * THREADS;                                      \
            int hh = idx >> 3, c = idx & 7;                                   \
            cp_async16(sb + OFF_B + (((CUR) + 2) % 3) * B_BYTES +             \
                           swz128((uint32_t)(hh * 128 + c * 16)),             \
                       g_wt + (size_t)(n0 + hh) * DDIM + k0n + c * 8);        \
        }                                                                     \
        CP_COMMIT();                                                          \
    }                                                                         \
    if (hn1) {                                                                \
        const int k0a = ((KIDX) + 1) * K_HALF;                                \
        _Pragma("unroll")                                                     \
        for (int i = 0; i < 4; i++)                                           \
            ar[i] = *reinterpret_cast<const float4*>(                         \
                keys + (size_t)(row0 + amRow[i]) * DDIM + k0a + amQ * 4);     \
    }                                                                         \
    _Pragma("unroll")                                                         \
    for (int kf = 0; kf < 4; kf++) {                                          \
        uint32_t a[4][4], bb[4][2];                                           \
        _Pragma("unroll")                                                     \
        for (int mi = 0; mi < 4; mi++)                                        \
            ldm_x4(a[mi][0], a[mi][1], a[mi][2], a[mi][3],                    \
                   aBase[mi] + ckA[kf] + (CUR) * A_BYTES);                    \
        _Pragma("unroll")                                                     \
        for (int p = 0; p < 2; p++)                                           \
            ldm_x4(bb[2*p][0], bb[2*p][1], bb[2*p+1][0], bb[2*p+1][1],        \
                   bBase[p] + ckB[kf] + (CUR) * B_BYTES);                     \
        mma_all(acc, a, bb);                                                  \
    }                                                                         \
    if (hn1) {                                                                \
        _Pragma("unroll")                                                     \
        for (int i = 0; i < 4; i++) {                                         \
            union { __half2 h2[2]; uint2 u; } cv;                             \
            cv.h2[0] = __floats2half2_rn(ar[i].x, ar[i].y);                   \
            cv.h2[1] = __floats2half2_rn(ar[i].z, ar[i].w);                   \
            STS64(stsA[i] + (((CUR) + 1) % 3) * A_BYTES, cv.u.x, cv.u.y);     \
        }                                                                     \
    }                                                                         \
    DO_WAIT_##W();                                                            \
    __syncthreads();                                                          \
}

__global__ void __launch_bounds__(THREADS, 1)
attn_main_kernel(const float* __restrict__ keys,
                 const float* __restrict__ w_v,
                 float* __restrict__ out) {
    extern __shared__ char smem[];
    const uint32_t sb  = smem_u32(smem);
    const int tid  = threadIdx.x;
    const int wid  = tid >> 5;
    const int lane = tid & 31;
    const int warp_m = wid >> 3;     // 0..1
    const int warp_n = wid & 7;      // 0..7
    const int row0 = blockIdx.x * M_TILE;
    const int b    = row0 >> 13;     // 8192 rows per batch

    float* s_q   = reinterpret_cast<float*>(smem + OFF_Q);
    float* s_wv  = reinterpret_cast<float*>(smem + OFF_WV);
    float* s_out = reinterpret_cast<float*>(smem + OFF_OUT);  // [4][128]

    for (int i = tid; i < HDIM; i += THREADS) {
        s_q[i]  = g_q[b * HDIM + i];
        s_wv[i] = w_v[i];
    }

    // lane-invariant fragment geometry
    const int rowA  = warp_m * 64 + (lane & 15);
    const int colA8 = (lane >> 4) << 3;
    const int gB    = lane >> 3;
    const int rowB  = warp_n * 32 + (lane & 7) + ((gB >> 1) << 3);
    const int colB8 = (gB & 1) << 3;

    // precomputed ldmatrix addresses (swz identity, row&7 == lane&7)
    const uint32_t s7 = (uint32_t)((lane & 7) << 4);
    uint32_t aBase[4], bBase[2], ckA[4], ckB[4];
#pragma unroll
    for (int mi = 0; mi < 4; mi++)
        aBase[mi] = sb + OFF_A + (uint32_t)((rowA + mi * 16) * 128);
#pragma unroll
    for (int p = 0; p < 2; p++)
        bBase[p]  = sb + OFF_B + (uint32_t)((rowB + p * 16) * 128);
#pragma unroll
    for (int kf = 0; kf < 4; kf++) {
        ckA[kf] = ((uint32_t)((kf * 16 + colA8) * 2)) ^ s7;
        ckB[kf] = ((uint32_t)((kf * 16 + colB8) * 2)) ^ s7;
    }

    // A-loader: 4 x float4 per thread per stage
    const int amRow [4] = { (tid + 0*THREADS) >> 4, (tid + 1*THREADS) >> 4,
                            (tid + 2*THREADS) >> 4, (tid + 3*THREADS) >> 4 };
    const int amQ = tid & 15;
    const uint32_t sSts = (uint32_t)(((tid >> 4) & 7) << 4);
    uint32_t stsA[4];
#pragma unroll
    for (int i = 0; i < 4; i++)
        stsA[i] = sb + OFF_A + (uint32_t)(amRow[i] * 128) +
                  (((uint32_t)(amQ * 8)) ^ sSts);

    float sc[8];
#pragma unroll
    for (int i = 0; i < 8; i++) sc[i] = 0.f;

    __syncthreads();   // publish s_q / s_wv

#pragma unroll 1
    for (int nc = 0; nc < PASSES; nc++) {
        const int n0 = nc * N_TILE;
        float acc[4][4][4];
#pragma unroll
        for (int mi = 0; mi < 4; mi++)
#pragma unroll
            for (int nf = 0; nf < 4; nf++)
#pragma unroll
                for (int c = 0; c < 4; c++) acc[mi][nf][c] = 0.f;

        // ---- prologue: B0 -> buf0, B1 -> buf1 (separate groups), A0 -> buf0
        {
#pragma unroll
            for (int s = 0; s < 2; s++) {
#pragma unroll
                for (int i = 0; i < 4; i++) {
                    int idx = tid + i * THREADS;
                    int h = idx >> 3, c = idx & 7;
                    cp_async16(sb + OFF_B + s * B_BYTES +
                                   swz128((uint32_t)(h * 128 + c * 16)),
                               g_wt + (size_t)(n0 + h) * DDIM + s * K_HALF + c * 8);
                }
                CP_COMMIT();
            }
            float4 ar[4];
#pragma unroll
            for (int i = 0; i < 4; i++)
                ar[i] = *reinterpret_cast<const float4*>(
                    keys + (size_t)(row0 + amRow[i]) * DDIM + 0 + amQ * 4);
#pragma unroll
            for (int i = 0; i < 4; i++) {
                union { __half2 h2[2]; uint2 u; } cv;
                cv.h2[0] = __floats2half2_rn(ar[i].x, ar[i].y);
                cv.h2[1] = __floats2half2_rn(ar[i].z, ar[i].w);
                STS64(stsA[i], cv.u.x, cv.u.y);
            }
            DO_WAIT_1();        // B0 complete; B1 may still fly
            __syncthreads();
        }

        // ---- 16 stages: 4 triples + 4 peeled with exact wait depths ----
#pragma unroll 1
        for (int ks = 0; ks < 12; ks += 3) {
            STAGE(0, ks,     1);
            STAGE(1, ks + 1, 1);
            STAGE(2, ks + 2, 1);
        }
        STAGE(0, 12, 1);
        STAGE(1, 13, 1);
        STAGE(2, 14, 0);
        STAGE(0, 15, 9);

        // ---- fused epilogue for this h-chunk ----
        const int t2 = (lane & 3) * 2;
#pragma unroll
        for (int mi = 0; mi < 4; mi++) {
#pragma unroll
            for (int nf = 0; nf < 4; nf++) {
                const int n = n0 + warp_n * 32 + nf * 8 + t2;
                const float q0 = s_q[n],  q1 = s_q[n + 1];
                const float w0 = s_wv[n], w1 = s_wv[n + 1];
                sc[mi*2]     = fmaf(fast_tanh(acc[mi][nf][0] + q0), w0, sc[mi*2]);
                sc[mi*2]     = fmaf(fast_tanh(acc[mi][nf][1] + q1), w1, sc[mi*2]);
                sc[mi*2 + 1] = fmaf(fast_tanh(acc[mi][nf][2] + q0), w0, sc[mi*2+1]);
                sc[mi*2 + 1] = fmaf(fast_tanh(acc[mi][nf][3] + q1), w1, sc[mi*2+1]);
            }
        }
    }

    // ---- reduce scores ----
#pragma unroll
    for (int i = 0; i < 8; i++) {
        sc[i] += __shfl_xor_sync(0xFFFFFFFFu, sc[i], 1);
        sc[i] += __shfl_xor_sync(0xFFFFFFFFu, sc[i], 2);
    }
    __syncthreads();
    if ((lane & 3) == 0 && (warp_n & 1) == 0) {
        const int g = lane >> 2;
        float* slot = s_out + (warp_n >> 1) * M_TILE;
#pragma unroll
        for (int mi = 0; mi < 4; mi++) {
            const int r0 = warp_m * 64 + mi * 16 + g;
            slot[r0]     = sc[mi*2];
            slot[r0 + 8] = sc[mi*2 + 1];
        }
    }
    __syncthreads();
    if ((lane & 3) == 0 && (warp_n & 1) == 1) {
        const int g = lane >> 2;
        float* slot = s_out + (warp_n >> 1) * M_TILE;
#pragma unroll
        for (int mi = 0; mi < 4; mi++) {
            const int r0 = warp_m * 64 + mi * 16 + g;
            slot[r0]     += sc[mi*2];
            slot[r0 + 8] += sc[mi*2 + 1];
        }
    }
    __syncthreads();
    if (tid < M_TILE) {
        float v = (s_out[tid] + s_out[M_TILE + tid]) +
                  (s_out[2 * M_TILE + tid] + s_out[3 * M_TILE + tid]);
        out[row0 + tid] = v;
    }
}

// ============================ launch ======================================
extern "C" void kernel_launch(void* const* d_in, const int* in_sizes, int n_in,
                              void* d_out, int out_size) {
    const float* queries = (const float*)d_in[0];
    const float* keys    = (const float*)d_in[1];
    const float* W_q     = (const float*)d_in[2];
    const float* W_k     = (const float*)d_in[3];
    const float* w_v     = (const float*)d_in[4];
    float* out = (float*)d_out;

    cudaFuncSetAttribute(attn_main_kernel,
                         cudaFuncAttributeMaxDynamicSharedMemorySize, SMEM_TOTAL);

    prep_kernel<<<WCONV_BLOCKS + QPART_BLOCKS, 256>>>(W_k, queries, W_q);
    qcombine_kernel<<<(B_SZ * HDIM) / 256, 256>>>();
    attn_main_kernel<<<NUM_TILES, THREADS, SMEM_TOTAL>>>(keys, w_v, out);
}

// round 11
// speedup vs baseline: 1.2812x; 1.0608x over previous
#include <cuda_runtime.h>
#include <cuda_fp16.h>
#include <cstdint>

// ============================ problem constants ============================
namespace {
constexpr int B_SZ  = 16;
constexpr int LKDIM = 8192;
constexpr int DDIM  = 1024;
constexpr int HDIM  = 1024;
constexpr int BL    = B_SZ * LKDIM;          // 131072 GEMM rows

constexpr int M_TILE  = 128;
constexpr int N_TILE  = 256;                 // h-chunk per pass
constexpr int PASSES  = HDIM / N_TILE;       // 4
constexpr int K_HALF  = 64;                  // halves per K stage (128B rows)
constexpr int K_STEPS = DDIM / K_HALF;       // 16
constexpr int THREADS = 512;                 // 16 warps: 2(M) x 8(N)
constexpr int NUM_TILES = BL / M_TILE;       // 1024 CTAs

constexpr int A_BYTES = M_TILE * 128;        // 16 KB / buf
constexpr int B_BYTES = N_TILE * 128;        // 32 KB / buf

// dynamic SMEM: 4 A bufs + 4 B bufs (2-stage barrier windows)
constexpr int OFF_Q   = 0;                       // 1024 f32
constexpr int OFF_WV  = OFF_Q  + HDIM * 4;       // 1024 f32
constexpr int OFF_OUT = OFF_WV + HDIM * 4;       // 128*4 f32 partial slots
constexpr int OFF_A   = 10240;                   // 4 bufs
constexpr int OFF_B   = OFF_A + 4 * A_BYTES;     // 75776
constexpr int SMEM_TOTAL = OFF_B + 4 * B_BYTES;  // 206848 B (1 CTA/SM)

// prep kernel
constexpr int WCONV_BLOCKS = (HDIM * DDIM) / 256;   // 4096
constexpr int QPART_BLOCKS = B_SZ * 16;             // 256
} // namespace

// ============================ device scratch ==============================
__device__ float  g_qp[4 * B_SZ * HDIM];  // q partials over 4 d-slices
__device__ __half g_wt[HDIM * DDIM];      // W_k^T: [h][d] fp16

// ============================ helpers =====================================
__device__ __forceinline__ uint32_t smem_u32(const void* p) {
    uint32_t a;
    asm("{ .reg .u64 t; cvta.to.shared.u64 t, %1; cvt.u32.u64 %0, t; }"
        : "=r"(a) : "l"(p));
    return a;
}
__device__ __forceinline__ uint32_t swz128(uint32_t off) {
    return off ^ ((off >> 3) & 0x70);
}
__device__ __forceinline__ void ldm_x4(uint32_t& r0, uint32_t& r1,
                                       uint32_t& r2, uint32_t& r3, uint32_t addr) {
    asm volatile("ldmatrix.sync.aligned.m8n8.x4.shared.b16 {%0,%1,%2,%3}, [%4];"
                 : "=r"(r0), "=r"(r1), "=r"(r2), "=r"(r3) : "r"(addr));
}
__device__ __forceinline__ void mma16816(float* c, const uint32_t* a, const uint32_t* b) {
    asm volatile(
        "mma.sync.aligned.m16n8k16.row.col.f32.f16.f16.f32 "
        "{%0,%1,%2,%3}, {%4,%5,%6,%7}, {%8,%9}, {%0,%1,%2,%3};"
        : "+f"(c[0]), "+f"(c[1]), "+f"(c[2]), "+f"(c[3])
        : "r"(a[0]), "r"(a[1]), "r"(a[2]), "r"(a[3]), "r"(b[0]), "r"(b[1]));
}
__device__ __forceinline__ void cp_async16(uint32_t saddr, const void* gaddr) {
    asm volatile("cp.async.cg.shared.global [%0], [%1], 16;"
                 :: "r"(saddr), "l"(gaddr) : "memory");
}
#define CP_COMMIT() asm volatile("cp.async.commit_group;" ::: "memory")
#define CP_WAIT0()  asm volatile("cp.async.wait_group 0;"  ::: "memory")
#define STS64(addr, vx, vy) \
    asm volatile("st.shared.v2.u32 [%0], {%1,%2};" \
                 :: "r"(addr), "r"(vx), "r"(vy) : "memory")

__device__ __forceinline__ float fast_tanh(float x) {
    float r;
    asm("tanh.approx.f32 %0, %1;" : "=f"(r) : "f"(x));
    return r;
}

// ============================ prep kernel =================================
__global__ void prep_kernel(const float* __restrict__ W_k,
                            const float* __restrict__ queries,
                            const float* __restrict__ W_q) {
    if (blockIdx.x < WCONV_BLOCKS) {
        int idx = blockIdx.x * 256 + threadIdx.x;   // over D*H
        int d = idx >> 10, h = idx & 1023;
        g_wt[(size_t)h * DDIM + d] = __float2half_rn(W_k[idx]);
    } else {
        const int qb  = blockIdx.x - WCONV_BLOCKS;  // 0..255
        const int b   = qb >> 4;
        const int hc  = (qb >> 2) & 3;
        const int dc  = qb & 3;
        __shared__ float sq[256];
        sq[threadIdx.x] = queries[b * DDIM + dc * 256 + threadIdx.x];
        __syncthreads();
        const int h = hc * 256 + threadIdx.x;
        float acc = 0.f;
        const float* w = W_q + (size_t)(dc * 256) * HDIM + h;
#pragma unroll 8
        for (int d = 0; d < 256; d++)
            acc = fmaf(sq[d], w[(size_t)d * HDIM], acc);
        g_qp[(dc * B_SZ + b) * HDIM + h] = acc;
    }
}

// ============================ main fused kernel ===========================
// Compute one K-stage from buffer BUF (compile-time).
#define COMPUTE(BUF)                                                          \
{                                                                             \
    _Pragma("unroll")                                                         \
    for (int kf = 0; kf < 4; kf++) {                                          \
        uint32_t a[4][4], bb[4][2];                                           \
        _Pragma("unroll")                                                     \
        for (int mi = 0; mi < 4; mi++)                                        \
            ldm_x4(a[mi][0], a[mi][1], a[mi][2], a[mi][3],                    \
                   aBase[mi] + ckA[kf] + (BUF) * A_BYTES);                    \
        _Pragma("unroll")                                                     \
        for (int p = 0; p < 2; p++)                                           \
            ldm_x4(bb[2*p][0], bb[2*p][1], bb[2*p+1][0], bb[2*p+1][1],        \
                   bBase[p] + ckB[kf] + (BUF) * B_BYTES);                     \
        _Pragma("unroll")                                                     \
        for (int mi = 0; mi < 4; mi++)                                        \
            _Pragma("unroll")                                                 \
            for (int nf = 0; nf < 4; nf++)                                    \
                mma16816(acc[mi][nf], a[mi], bb[nf]);                         \
    }                                                                         \
}

#define LDG_A(K)                                                              \
{                                                                             \
    const int k0a = (K) * K_HALF;                                             \
    _Pragma("unroll")                                                         \
    for (int i = 0; i < 4; i++)                                               \
        ar[i] = *reinterpret_cast<const float4*>(                             \
            keys + (size_t)(row0 + amRow[i]) * DDIM + k0a + amQ * 4);         \
}

#define STS_A(BUF)                                                            \
{                                                                             \
    _Pragma("unroll")                                                         \
    for (int i = 0; i < 4; i++) {                                             \
        union { __half2 h2[2]; uint2 u; } cv;                                 \
        cv.h2[0] = __floats2half2_rn(ar[i].x, ar[i].y);                       \
        cv.h2[1] = __floats2half2_rn(ar[i].z, ar[i].w);                       \
        STS64(stsA[i] + (BUF) * A_BYTES, cv.u.x, cv.u.y);                     \
    }                                                                         \
}

#define CP_B(K, BUF)                                                          \
{                                                                             \
    const int k0n = (K) * K_HALF;                                             \
    _Pragma("unroll")                                                         \
    for (int i = 0; i < 4; i++) {                                             \
        int idx = tid + i * THREADS;                                          \
        int hh = idx >> 3, c = idx & 7;                                       \
        cp_async16(sb + OFF_B + (BUF) * B_BYTES +                             \
                       swz128((uint32_t)(hh * 128 + c * 16)),                 \
                   g_wt + (size_t)(n0 + hh) * DDIM + k0n + c * 8);            \
    }                                                                         \
}

// Window: stages K0 (buf B0), K0+1 (buf B1); prefetch K0+2,K0+3 into B0^2,B1^2.
#define WINDOW(B0, B1, K0, IS_LAST)                                           \
{                                                                             \
    float4 ar[4];                                                             \
    if (!(IS_LAST)) {                                                         \
        CP_B((K0) + 2, (B0) ^ 2);                                             \
        CP_B((K0) + 3, (B1) ^ 2);                                             \
        CP_COMMIT();                                                          \
        LDG_A((K0) + 2);                                                      \
    }                                                                         \
    COMPUTE(B0);                                                              \
    if (!(IS_LAST)) {                                                         \
        STS_A((B0) ^ 2);                                                      \
        LDG_A((K0) + 3);                                                      \
    }                                                                         \
    COMPUTE(B1);                                                              \
    if (!(IS_LAST)) {                                                         \
        STS_A((B1) ^ 2);                                                      \
        CP_WAIT0();                                                           \
    }                                                                         \
    __syncthreads();                                                          \
}

__global__ void __launch_bounds__(THREADS, 1)
attn_main_kernel(const float* __restrict__ keys,
                 const float* __restrict__ w_v,
                 float* __restrict__ out) {
    extern __shared__ char smem[];
    const uint32_t sb  = smem_u32(smem);
    const int tid  = threadIdx.x;
    const int wid  = tid >> 5;
    const int lane = tid & 31;
    const int warp_m = wid >> 3;     // 0..1
    const int warp_n = wid & 7;      // 0..7
    const int row0 = blockIdx.x * M_TILE;
    const int b    = row0 >> 13;     // 8192 rows per batch

    float* s_q   = reinterpret_cast<float*>(smem + OFF_Q);
    float* s_wv  = reinterpret_cast<float*>(smem + OFF_WV);
    float* s_out = reinterpret_cast<float*>(smem + OFF_OUT);  // [4][128]

    // q-combine fused here (pairwise, matches old qcombine order)
    for (int i = tid; i < HDIM; i += THREADS) {
        int gi = b * HDIM + i;
        s_q[i]  = (g_qp[gi] + g_qp[B_SZ * HDIM + gi]) +
                  (g_qp[2 * B_SZ * HDIM + gi] + g_qp[3 * B_SZ * HDIM + gi]);
        s_wv[i] = w_v[i];
    }

    // lane-invariant fragment geometry
    const int rowA  = warp_m * 64 + (lane & 15);
    const int colA8 = (lane >> 4) << 3;
    const int gB    = lane >> 3;
    const int rowB  = warp_n * 32 + (lane & 7) + ((gB >> 1) << 3);
    const int colB8 = (gB & 1) << 3;

    // precomputed ldmatrix addresses (swz identity, row&7 == lane&7)
    const uint32_t s7 = (uint32_t)((lane & 7) << 4);
    uint32_t aBase[4], bBase[2], ckA[4], ckB[4];
#pragma unroll
    for (int mi = 0; mi < 4; mi++)
        aBase[mi] = sb + OFF_A + (uint32_t)((rowA + mi * 16) * 128);
#pragma unroll
    for (int p = 0; p < 2; p++)
        bBase[p]  = sb + OFF_B + (uint32_t)((rowB + p * 16) * 128);
#pragma unroll
    for (int kf = 0; kf < 4; kf++) {
        ckA[kf] = ((uint32_t)((kf * 16 + colA8) * 2)) ^ s7;
        ckB[kf] = ((uint32_t)((kf * 16 + colB8) * 2)) ^ s7;
    }

    // A-loader: 4 x float4 per thread per stage
    const int amRow [4] = { (tid + 0*THREADS) >> 4, (tid + 1*THREADS) >> 4,
                            (tid + 2*THREADS) >> 4, (tid + 3*THREADS) >> 4 };
    const int amQ = tid & 15;
    const uint32_t sSts = (uint32_t)(((tid >> 4) & 7) << 4);
    uint32_t stsA[4];
#pragma unroll
    for (int i = 0; i < 4; i++)
        stsA[i] = sb + OFF_A + (uint32_t)(amRow[i] * 128) +
                  (((uint32_t)(amQ * 8)) ^ sSts);

    float sc[8];
#pragma unroll
    for (int i = 0; i < 8; i++) sc[i] = 0.f;

    __syncthreads();   // publish s_q / s_wv

#pragma unroll 1
    for (int nc = 0; nc < PASSES; nc++) {
        const int n0 = nc * N_TILE;
        float acc[4][4][4];
#pragma unroll
        for (int mi = 0; mi < 4; mi++)
#pragma unroll
            for (int nf = 0; nf < 4; nf++)
#pragma unroll
                for (int c = 0; c < 4; c++) acc[mi][nf][c] = 0.f;

        // ---- prologue: B0->buf0, B1->buf1; A0->buf0, A1->buf1 ----
        {
            CP_B(0, 0);
            CP_B(1, 1);
            CP_COMMIT();
            float4 ar[4];
            LDG_A(0);
            STS_A(0);
            LDG_A(1);
            STS_A(1);
            CP_WAIT0();
            __syncthreads();
        }

        // ---- 8 windows of 2 stages each ----
#pragma unroll 1
        for (int k0 = 0; k0 < 12; k0 += 4) {
            WINDOW(0, 1, k0,     false);
            WINDOW(2, 3, k0 + 2, false);
        }
        WINDOW(0, 1, 12, false);
        WINDOW(2, 3, 14, true);

        // ---- fused epilogue for this h-chunk ----
        const int t2 = (lane & 3) * 2;
#pragma unroll
        for (int mi = 0; mi < 4; mi++) {
#pragma unroll
            for (int nf = 0; nf < 4; nf++) {
                const int n = n0 + warp_n * 32 + nf * 8 + t2;
                const float q0 = s_q[n],  q1 = s_q[n + 1];
                const float w0 = s_wv[n], w1 = s_wv[n + 1];
                sc[mi*2]     = fmaf(fast_tanh(acc[mi][nf][0] + q0), w0, sc[mi*2]);
                sc[mi*2]     = fmaf(fast_tanh(acc[mi][nf][1] + q1), w1, sc[mi*2]);
                sc[mi*2 + 1] = fmaf(fast_tanh(acc[mi][nf][2] + q0), w0, sc[mi*2+1]);
                sc[mi*2 + 1] = fmaf(fast_tanh(acc[mi][nf][3] + q1), w1, sc[mi*2+1]);
            }
        }
    }

    // ---- reduce scores ----
#pragma unroll
    for (int i = 0; i < 8; i++) {
        sc[i] += __shfl_xor_sync(0xFFFFFFFFu, sc[i], 1);
        sc[i] += __shfl_xor_sync(0xFFFFFFFFu, sc[i], 2);
    }
    __syncthreads();
    if ((lane & 3) == 0 && (warp_n & 1) == 0) {
        const int g = lane >> 2;
        float* slot = s_out + (warp_n >> 1) * M_TILE;
#pragma unroll
        for (int mi = 0; mi < 4; mi++) {
            const int r0 = warp_m * 64 + mi * 16 + g;
            slot[r0]     = sc[mi*2];
            slot[r0 + 8] = sc[mi*2 + 1];
        }
    }
    __syncthreads();
    if ((lane & 3) == 0 && (warp_n & 1) == 1) {
        const int g = lane >> 2;
        float* slot = s_out + (warp_n >> 1) * M_TILE;
#pragma unroll
        for (int mi = 0; mi < 4; mi++) {
            const int r0 = warp_m * 64 + mi * 16 + g;
            slot[r0]     += sc[mi*2];
            slot[r0 + 8] += sc[mi*2 + 1];
        }
    }
    __syncthreads();
    if (tid < M_TILE) {
        float v = (s_out[tid] + s_out[M_TILE + tid]) +
                  (s_out[2 * M_TILE + tid] + s_out[3 * M_TILE + tid]);
        out[row0 + tid] = v;
    }
}

// ============================ launch ======================================
extern "C" void kernel_launch(void* const* d_in, const int* in_sizes, int n_in,
                              void* d_out, int out_size) {
    const float* queries = (const float*)d_in[0];
    const float* keys    = (const float*)d_in[1];
    const float* W_q     = (const float*)d_in[2];
    const float* W_k     = (const float*)d_in[3];
    const float* w_v     = (const float*)d_in[4];
    float* out = (float*)d_out;

    cudaFuncSetAttribute(attn_main_kernel,
                         cudaFuncAttributeMaxDynamicSharedMemorySize, SMEM_TOTAL);

    prep_kernel<<<WCONV_BLOCKS + QPART_BLOCKS, 256>>>(W_k, queries, W_q);
    attn_main_kernel<<<NUM_TILES, THREADS, SMEM_TOTAL>>>(keys, w_v, out);
}